// round 1
// baseline (speedup 1.0000x reference)
#include <cuda_runtime.h>
#include <math.h>

// Problem constants (fixed shapes from the reference)
#define BT   16          // B*T
#define DCH  256         // channels D
#define HW   1024        // 32*32
#define CHW  (DCH*HW)    // 262144

// ---------------- static scratch ----------------
__device__ float g_q[BT * CHW];
__device__ float g_k[BT * CHW];
__device__ float g_v[BT * CHW];
__device__ float g_qs[2 * 524288];   // [b, L, dd] ; L*dd == 524288 for every scale
__device__ float g_ks[2 * 524288];
__device__ float g_vs[2 * 524288];
__device__ float g_att[BT * CHW];    // concat of per-scale attention outputs
__device__ float g_sc[2ll * 8192 * 8192];  // scores scratch (512 MB, max over scales)

// =====================================================================
// 1) Fused QKV projection: q/k/v[bt, o, p] = sum_c W[o,c] * x[bt, c, p] + b[o]
//    GEMM per bt: M=256 (o), N=1024 (p), K=256. Tile 64x64, BK=16.
// =====================================================================
__global__ void qkv_proj(const float* __restrict__ x,
                         const float* __restrict__ wq, const float* __restrict__ bq,
                         const float* __restrict__ wk, const float* __restrict__ bk,
                         const float* __restrict__ wv, const float* __restrict__ bv)
{
    const int bt    = blockIdx.z;
    const int oBase = blockIdx.y * 64;
    const int pBase = blockIdx.x * 64;

    __shared__ float Aq[16][68], Ak[16][68], Av[16][68];
    __shared__ float Bs[16][64];

    const int tid = threadIdx.x;
    const int tx  = tid & 15, ty = tid >> 4;
    const int lr  = tid >> 2;            // 0..63 (row for A loads)
    const int lk  = (tid & 3) * 4;       // 0,4,8,12
    const int kkl = tid >> 4;            // 0..15 (k row for B loads)
    const int cl  = (tid & 15) * 4;      // col*4 for B loads

    float accq[4][4] = {}, acck[4][4] = {}, accv[4][4] = {};
    const float* xb = x + (size_t)bt * CHW + pBase;

    for (int k0 = 0; k0 < 256; k0 += 16) {
        float4 aq = *(const float4*)&wq[(oBase + lr) * 256 + k0 + lk];
        float4 ak = *(const float4*)&wk[(oBase + lr) * 256 + k0 + lk];
        float4 av = *(const float4*)&wv[(oBase + lr) * 256 + k0 + lk];
        float4 b4 = *(const float4*)&xb[(size_t)(k0 + kkl) * HW + cl];
        __syncthreads();
        Aq[lk + 0][lr] = aq.x; Aq[lk + 1][lr] = aq.y; Aq[lk + 2][lr] = aq.z; Aq[lk + 3][lr] = aq.w;
        Ak[lk + 0][lr] = ak.x; Ak[lk + 1][lr] = ak.y; Ak[lk + 2][lr] = ak.z; Ak[lk + 3][lr] = ak.w;
        Av[lk + 0][lr] = av.x; Av[lk + 1][lr] = av.y; Av[lk + 2][lr] = av.z; Av[lk + 3][lr] = av.w;
        *(float4*)&Bs[kkl][cl] = b4;
        __syncthreads();
        #pragma unroll
        for (int kk = 0; kk < 16; kk++) {
            float4 aqv = *(const float4*)&Aq[kk][ty * 4];
            float4 akv = *(const float4*)&Ak[kk][ty * 4];
            float4 avv = *(const float4*)&Av[kk][ty * 4];
            float4 bv4 = *(const float4*)&Bs[kk][tx * 4];
            float aQ[4] = {aqv.x, aqv.y, aqv.z, aqv.w};
            float aK[4] = {akv.x, akv.y, akv.z, akv.w};
            float aV[4] = {avv.x, avv.y, avv.z, avv.w};
            float bb[4] = {bv4.x, bv4.y, bv4.z, bv4.w};
            #pragma unroll
            for (int i = 0; i < 4; i++)
                #pragma unroll
                for (int j = 0; j < 4; j++) {
                    accq[i][j] += aQ[i] * bb[j];
                    acck[i][j] += aK[i] * bb[j];
                    accv[i][j] += aV[i] * bb[j];
                }
        }
    }
    #pragma unroll
    for (int i = 0; i < 4; i++) {
        const int o = oBase + ty * 4 + i;
        const float bqv = bq[o], bkv = bk[o], bvv = bv[o];
        #pragma unroll
        for (int j = 0; j < 4; j++) {
            const int p = pBase + tx * 4 + j;
            const size_t off = (size_t)bt * CHW + (size_t)o * HW + p;
            g_q[off] = accq[i][j] + bqv;
            g_k[off] = acck[i][j] + bkv;
            g_v[off] = accv[i][j] + bvv;
        }
    }
}

// =====================================================================
// 2) Patch gather: qs/ks/vs[b, l, d] from q/k/v[bt, ch, pix]
//    l = (t*o + oy)*o + ox ; d = (c*p + py)*p + px ; qs scaled by 1/sqrt(dd)
// =====================================================================
__global__ void patch_qkv(int p, int o, int dd, int L, int sBase, float qscale)
{
    const int idx = blockIdx.x * 256 + threadIdx.x;
    const int total = 2 * L * dd;
    if (idx >= total) return;
    const int b   = idx / (L * dd);
    const int rem = idx % (L * dd);
    const int l   = rem / dd;
    const int d   = rem % dd;
    const int t   = l / (o * o);
    const int r2  = l % (o * o);
    const int oy  = r2 / o, ox = r2 % o;
    const int c   = d / (p * p);
    const int r3  = d % (p * p);
    const int py  = r3 / p, px = r3 % p;
    const size_t src = ((size_t)(b * 8 + t) * DCH + (sBase + c)) * HW
                     + (oy * p + py) * 32 + (ox * p + px);
    g_qs[idx] = g_q[src] * qscale;
    g_ks[idx] = g_k[src];
    g_vs[idx] = g_v[src];
}

__global__ void zero_scores(int n)
{
    int i = blockIdx.x * 256 + threadIdx.x;
    if (i < n) g_sc[i] = 0.f;
}

// =====================================================================
// 3) Scores: S[b, l, m] = sum_d qs[b,l,d] * ks[b,m,d]   (NT GEMM, split-K opt)
// =====================================================================
__global__ void gemm_scores(int L, int dd, int splitK)
{
    const int bz    = blockIdx.z;
    const int batch = bz / splitK;
    const int ks    = bz % splitK;
    const int kLen  = dd / splitK;
    const float* A = g_qs + (size_t)batch * L * dd;
    const float* B = g_ks + (size_t)batch * L * dd;
    float*       C = g_sc + (size_t)batch * L * L;
    const int rowBase = blockIdx.y * 64;
    const int colBase = blockIdx.x * 64;

    __shared__ float As[16][68], Bs[16][68];
    const int tid = threadIdx.x;
    const int tx = tid & 15, ty = tid >> 4;
    const int lr = tid >> 2, lk = (tid & 3) * 4;
    float acc[4][4] = {};

    const int kEnd = ks * kLen + kLen;
    for (int k0 = ks * kLen; k0 < kEnd; k0 += 16) {
        float4 a4 = *(const float4*)&A[(size_t)(rowBase + lr) * dd + k0 + lk];
        float4 b4 = *(const float4*)&B[(size_t)(colBase + lr) * dd + k0 + lk];
        __syncthreads();
        As[lk + 0][lr] = a4.x; As[lk + 1][lr] = a4.y; As[lk + 2][lr] = a4.z; As[lk + 3][lr] = a4.w;
        Bs[lk + 0][lr] = b4.x; Bs[lk + 1][lr] = b4.y; Bs[lk + 2][lr] = b4.z; Bs[lk + 3][lr] = b4.w;
        __syncthreads();
        #pragma unroll
        for (int kk = 0; kk < 16; kk++) {
            float4 av4 = *(const float4*)&As[kk][ty * 4];
            float4 bv4 = *(const float4*)&Bs[kk][tx * 4];
            float a[4] = {av4.x, av4.y, av4.z, av4.w};
            float b[4] = {bv4.x, bv4.y, bv4.z, bv4.w};
            #pragma unroll
            for (int i = 0; i < 4; i++)
                #pragma unroll
                for (int j = 0; j < 4; j++)
                    acc[i][j] += a[i] * b[j];
        }
    }
    #pragma unroll
    for (int i = 0; i < 4; i++)
        #pragma unroll
        for (int j = 0; j < 4; j++) {
            const int row = rowBase + ty * 4 + i;
            const int col = colBase + tx * 4 + j;
            if (splitK == 1) C[(size_t)row * L + col] = acc[i][j];
            else atomicAdd(&C[(size_t)row * L + col], acc[i][j]);
        }
}

// =====================================================================
// 4) Row softmax over g_sc (in place). One block per row.
// =====================================================================
__global__ void softmax_rows(int L)
{
    float* row = g_sc + (size_t)blockIdx.x * L;
    const int tid = threadIdx.x;
    __shared__ float red[256];

    float m = -1e30f;
    for (int i = tid; i < L; i += 256) m = fmaxf(m, row[i]);
    red[tid] = m; __syncthreads();
    for (int s = 128; s > 0; s >>= 1) {
        if (tid < s) red[tid] = fmaxf(red[tid], red[tid + s]);
        __syncthreads();
    }
    m = red[0];
    __syncthreads();

    float sum = 0.f;
    for (int i = tid; i < L; i += 256) {
        float e = __expf(row[i] - m);
        row[i] = e;
        sum += e;
    }
    red[tid] = sum; __syncthreads();
    for (int s = 128; s > 0; s >>= 1) {
        if (tid < s) red[tid] += red[tid + s];
        __syncthreads();
    }
    const float inv = 1.0f / red[0];
    for (int i = tid; i < L; i += 256) row[i] *= inv;
}

// =====================================================================
// 5) P·V (NN GEMM) with fused un-patch scatter into g_att
// =====================================================================
__global__ void gemm_pv(int L, int dd, int p, int o, int sBase)
{
    const int batch = blockIdx.z;
    const float* A = g_sc + (size_t)batch * L * L;
    const float* B = g_vs + (size_t)batch * L * dd;
    const int rowBase = blockIdx.y * 64;
    const int colBase = blockIdx.x * 64;

    __shared__ float As[16][68];
    __shared__ float Bs[16][64];
    const int tid = threadIdx.x;
    const int tx = tid & 15, ty = tid >> 4;
    const int lr = tid >> 2, lk = (tid & 3) * 4;
    const int kkl = tid >> 4, cl = (tid & 15) * 4;
    float acc[4][4] = {};

    for (int k0 = 0; k0 < L; k0 += 16) {
        float4 a4 = *(const float4*)&A[(size_t)(rowBase + lr) * L + k0 + lk];
        float4 b4 = *(const float4*)&B[(size_t)(k0 + kkl) * dd + colBase + cl];
        __syncthreads();
        As[lk + 0][lr] = a4.x; As[lk + 1][lr] = a4.y; As[lk + 2][lr] = a4.z; As[lk + 3][lr] = a4.w;
        *(float4*)&Bs[kkl][cl] = b4;
        __syncthreads();
        #pragma unroll
        for (int kk = 0; kk < 16; kk++) {
            float4 av4 = *(const float4*)&As[kk][ty * 4];
            float4 bv4 = *(const float4*)&Bs[kk][tx * 4];
            float a[4] = {av4.x, av4.y, av4.z, av4.w};
            float b[4] = {bv4.x, bv4.y, bv4.z, bv4.w};
            #pragma unroll
            for (int i = 0; i < 4; i++)
                #pragma unroll
                for (int j = 0; j < 4; j++)
                    acc[i][j] += a[i] * b[j];
        }
    }
    #pragma unroll
    for (int i = 0; i < 4; i++) {
        const int l  = rowBase + ty * 4 + i;
        const int t  = l / (o * o);
        const int r2 = l % (o * o);
        const int oy = r2 / o, ox = r2 % o;
        #pragma unroll
        for (int j = 0; j < 4; j++) {
            const int d  = colBase + tx * 4 + j;
            const int c  = d / (p * p);
            const int r3 = d % (p * p);
            const int py = r3 / p, px = r3 % p;
            const size_t dst = ((size_t)(batch * 8 + t) * DCH + sBase + c) * HW
                             + (oy * p + py) * 32 + (ox * p + px);
            g_att[dst] = acc[i][j];
        }
    }
}

// =====================================================================
// 6) 3x3 SAME conv (implicit GEMM, K=256*9) + bias + LeakyReLU(0.2)
// =====================================================================
__global__ void conv3_leaky(const float* __restrict__ wo, const float* __restrict__ bo,
                            float* __restrict__ out)
{
    const int bt    = blockIdx.z;
    const int oBase = blockIdx.y * 64;
    const int pBase = blockIdx.x * 64;

    __shared__ float As[16][68];
    __shared__ float Bs[16][64];
    const int tid = threadIdx.x;
    const int tx = tid & 15, ty = tid >> 4;
    const int lr = tid >> 2, lk = (tid & 3) * 4;
    const int kkl = tid >> 4, cl = (tid & 15) * 4;
    float acc[4][4] = {};
    const float* inb = g_att + (size_t)bt * CHW;

    for (int k0 = 0; k0 < 2304; k0 += 16) {
        float4 a4 = *(const float4*)&wo[(size_t)(oBase + lr) * 2304 + k0 + lk];
        const int k  = k0 + kkl;
        const int ic = k / 9;
        const int r  = k % 9;
        const int ky = r / 3 - 1, kx = r % 3 - 1;
        float bv[4];
        #pragma unroll
        for (int q = 0; q < 4; q++) {
            const int pp = pBase + cl + q;
            const int y = (pp >> 5) + ky;
            const int xx = (pp & 31) + kx;
            bv[q] = (y >= 0 && y < 32 && xx >= 0 && xx < 32)
                  ? inb[(size_t)ic * HW + y * 32 + xx] : 0.f;
        }
        __syncthreads();
        As[lk + 0][lr] = a4.x; As[lk + 1][lr] = a4.y; As[lk + 2][lr] = a4.z; As[lk + 3][lr] = a4.w;
        Bs[kkl][cl + 0] = bv[0]; Bs[kkl][cl + 1] = bv[1];
        Bs[kkl][cl + 2] = bv[2]; Bs[kkl][cl + 3] = bv[3];
        __syncthreads();
        #pragma unroll
        for (int kk = 0; kk < 16; kk++) {
            float4 av4 = *(const float4*)&As[kk][ty * 4];
            float4 bv4 = *(const float4*)&Bs[kk][tx * 4];
            float a[4] = {av4.x, av4.y, av4.z, av4.w};
            float b[4] = {bv4.x, bv4.y, bv4.z, bv4.w};
            #pragma unroll
            for (int i = 0; i < 4; i++)
                #pragma unroll
                for (int j = 0; j < 4; j++)
                    acc[i][j] += a[i] * b[j];
        }
    }
    #pragma unroll
    for (int i = 0; i < 4; i++) {
        const int o = oBase + ty * 4 + i;
        const float bias = bo[o];
        #pragma unroll
        for (int j = 0; j < 4; j++) {
            const int p = pBase + tx * 4 + j;
            float v = acc[i][j] + bias;
            v = (v > 0.f) ? v : 0.2f * v;
            out[(size_t)bt * CHW + (size_t)o * HW + p] = v;
        }
    }
}

// =====================================================================
// Launch
// =====================================================================
extern "C" void kernel_launch(void* const* d_in, const int* in_sizes, int n_in,
                              void* d_out, int out_size)
{
    (void)in_sizes; (void)n_in; (void)out_size;
    const float* x  = (const float*)d_in[0];
    // d_in[1] = m : dead code in the reference (masked_fill result discarded)
    const float* wq = (const float*)d_in[2];
    const float* bq = (const float*)d_in[3];
    const float* wk = (const float*)d_in[4];
    const float* bk = (const float*)d_in[5];
    const float* wv = (const float*)d_in[6];
    const float* bv = (const float*)d_in[7];
    const float* wo = (const float*)d_in[8];
    const float* bo = (const float*)d_in[9];
    float* out = (float*)d_out;

    qkv_proj<<<dim3(16, 4, 16), 256>>>(x, wq, bq, wk, bk, wv, bv);

    struct ScaleCfg { int p, o, dd, L, sBase, splitK; };
    const ScaleCfg cfgs[4] = {
        {8,  4, 4096,  128,   0, 8},
        {4,  8, 1024,  512,  64, 4},
        {2, 16,  256, 2048, 128, 1},
        {1, 32,   64, 8192, 192, 1},
    };

    for (int s = 0; s < 4; s++) {
        const ScaleCfg c = cfgs[s];
        const int total = 2 * c.L * c.dd;
        const float qscale = 1.0f / sqrtf((float)c.dd);
        patch_qkv<<<(total + 255) / 256, 256>>>(c.p, c.o, c.dd, c.L, c.sBase, qscale);
        if (c.splitK > 1) {
            const int n = 2 * c.L * c.L;
            zero_scores<<<(n + 255) / 256, 256>>>(n);
        }
        gemm_scores<<<dim3(c.L / 64, c.L / 64, 2 * c.splitK), 256>>>(c.L, c.dd, c.splitK);
        softmax_rows<<<2 * c.L, 256>>>(c.L);
        gemm_pv<<<dim3(c.dd / 64, c.L / 64, 2), 256>>>(c.L, c.dd, c.p, c.o, c.sBase);
    }

    conv3_leaky<<<dim3(16, 4, 16), 256>>>(wo, bo, out);
}

// round 2
// speedup vs baseline: 1.5315x; 1.5315x over previous
#include <cuda_runtime.h>
#include <math.h>

// Problem constants (fixed shapes from the reference)
#define BT   16          // B*T
#define DCH  256         // channels D
#define HW   1024        // 32*32
#define CHW  (DCH*HW)    // 262144

// ---------------- static scratch ----------------
__device__ float g_q[BT * CHW];
__device__ float g_k[BT * CHW];
__device__ float g_v[BT * CHW];
__device__ float g_qs[2 * 524288];   // [b, L, dd] ; L*dd == 524288 for every scale
__device__ float g_ks[2 * 524288];
__device__ float g_vs[2 * 524288];
__device__ float g_att[BT * CHW];    // concat of per-scale attention outputs
__device__ float g_sc[2ll * 8192 * 8192];  // scores scratch (512 MB, max over scales)

// ---------------- tf32 mma helpers ----------------
__device__ __forceinline__ unsigned f2tf(float f) {
    unsigned u;
    asm("cvt.rna.tf32.f32 %0, %1;" : "=r"(u) : "f"(f));
    return u;
}

__device__ __forceinline__ void mma_tf32(float c[4],
                                         unsigned a0, unsigned a1, unsigned a2, unsigned a3,
                                         unsigned b0, unsigned b1)
{
    asm volatile(
        "mma.sync.aligned.m16n8k8.row.col.f32.tf32.tf32.f32 "
        "{%0,%1,%2,%3}, {%4,%5,%6,%7}, {%8,%9}, {%0,%1,%2,%3};"
        : "+f"(c[0]), "+f"(c[1]), "+f"(c[2]), "+f"(c[3])
        : "r"(a0), "r"(a1), "r"(a2), "r"(a3), "r"(b0), "r"(b1));
}

__device__ __forceinline__ uint4 tf4(float4 v) {
    uint4 u;
    u.x = f2tf(v.x); u.y = f2tf(v.y); u.z = f2tf(v.z); u.w = f2tf(v.w);
    return u;
}

// =====================================================================
// 1) Fused QKV projection (tf32 TC):
//    q/k/v[bt, o, p] = sum_c W[o,c] * x[bt, c, p] + b[o]
//    M=256(o), N=1024(p), K=256(c). Block 64x64, BK=16, 128 thr (2x2 warps).
// =====================================================================
__global__ void qkv_proj_tc(const float* __restrict__ x,
                            const float* __restrict__ wq, const float* __restrict__ bq,
                            const float* __restrict__ wk, const float* __restrict__ bk,
                            const float* __restrict__ wv, const float* __restrict__ bv)
{
    const int bt    = blockIdx.z;
    const int oBase = blockIdx.y * 64;
    const int pBase = blockIdx.x * 64;

    __shared__ unsigned Aq[64][20], Ak[64][20], Av[64][20];  // [M][K] pad 20
    __shared__ unsigned Bs[16][68];                          // [K][N] pad 68

    const int tid  = threadIdx.x;           // 128
    const int lane = tid & 31, warp = tid >> 5;
    const int wm = (warp & 1) * 32, wn = (warp >> 1) * 32;
    const int g = lane >> 2, t4 = lane & 3;

    const int rowA = tid >> 1;              // 0..63
    const int offA = (tid & 1) * 8;         // 0 or 8
    const int rowB = tid >> 3;              // 0..15
    const int offB = (tid & 7) * 8;         // 0..56

    float acc[3][2][4][4];
    #pragma unroll
    for (int s = 0; s < 3; s++)
        #pragma unroll
        for (int mt = 0; mt < 2; mt++)
            #pragma unroll
            for (int nt = 0; nt < 4; nt++)
                #pragma unroll
                for (int e = 0; e < 4; e++) acc[s][mt][nt][e] = 0.f;

    const float* xb = x + (size_t)bt * CHW;

    for (int k0 = 0; k0 < 256; k0 += 16) {
        float4 q0 = *(const float4*)&wq[(oBase + rowA) * 256 + k0 + offA];
        float4 q1 = *(const float4*)&wq[(oBase + rowA) * 256 + k0 + offA + 4];
        float4 k0v = *(const float4*)&wk[(oBase + rowA) * 256 + k0 + offA];
        float4 k1v = *(const float4*)&wk[(oBase + rowA) * 256 + k0 + offA + 4];
        float4 v0 = *(const float4*)&wv[(oBase + rowA) * 256 + k0 + offA];
        float4 v1 = *(const float4*)&wv[(oBase + rowA) * 256 + k0 + offA + 4];
        float4 b0 = *(const float4*)&xb[(size_t)(k0 + rowB) * HW + pBase + offB];
        float4 b1 = *(const float4*)&xb[(size_t)(k0 + rowB) * HW + pBase + offB + 4];
        __syncthreads();
        *(uint4*)&Aq[rowA][offA]     = tf4(q0);
        *(uint4*)&Aq[rowA][offA + 4] = tf4(q1);
        *(uint4*)&Ak[rowA][offA]     = tf4(k0v);
        *(uint4*)&Ak[rowA][offA + 4] = tf4(k1v);
        *(uint4*)&Av[rowA][offA]     = tf4(v0);
        *(uint4*)&Av[rowA][offA + 4] = tf4(v1);
        *(uint4*)&Bs[rowB][offB]     = tf4(b0);
        *(uint4*)&Bs[rowB][offB + 4] = tf4(b1);
        __syncthreads();
        #pragma unroll
        for (int kk = 0; kk < 16; kk += 8) {
            unsigned bf[4][2];
            #pragma unroll
            for (int nt = 0; nt < 4; nt++) {
                bf[nt][0] = Bs[kk + t4][wn + nt * 8 + g];
                bf[nt][1] = Bs[kk + t4 + 4][wn + nt * 8 + g];
            }
            #pragma unroll
            for (int mt = 0; mt < 2; mt++) {
                const int mr = wm + mt * 16 + g;
                unsigned aq0 = Aq[mr][kk + t4],     aq1 = Aq[mr + 8][kk + t4];
                unsigned aq2 = Aq[mr][kk + t4 + 4], aq3 = Aq[mr + 8][kk + t4 + 4];
                unsigned ak0 = Ak[mr][kk + t4],     ak1 = Ak[mr + 8][kk + t4];
                unsigned ak2 = Ak[mr][kk + t4 + 4], ak3 = Ak[mr + 8][kk + t4 + 4];
                unsigned av0 = Av[mr][kk + t4],     av1 = Av[mr + 8][kk + t4];
                unsigned av2 = Av[mr][kk + t4 + 4], av3 = Av[mr + 8][kk + t4 + 4];
                #pragma unroll
                for (int nt = 0; nt < 4; nt++) {
                    mma_tf32(acc[0][mt][nt], aq0, aq1, aq2, aq3, bf[nt][0], bf[nt][1]);
                    mma_tf32(acc[1][mt][nt], ak0, ak1, ak2, ak3, bf[nt][0], bf[nt][1]);
                    mma_tf32(acc[2][mt][nt], av0, av1, av2, av3, bf[nt][0], bf[nt][1]);
                }
            }
        }
    }

    #pragma unroll
    for (int mt = 0; mt < 2; mt++) {
        const int r0 = oBase + wm + mt * 16 + g;
        const float bq0 = bq[r0], bq1 = bq[r0 + 8];
        const float bk0 = bk[r0], bk1 = bk[r0 + 8];
        const float bv0 = bv[r0], bv1 = bv[r0 + 8];
        #pragma unroll
        for (int nt = 0; nt < 4; nt++) {
            const int c0 = pBase + wn + nt * 8 + 2 * t4;
            const size_t o0 = (size_t)bt * CHW + (size_t)r0 * HW + c0;
            const size_t o1 = (size_t)bt * CHW + (size_t)(r0 + 8) * HW + c0;
            *(float2*)&g_q[o0] = make_float2(acc[0][mt][nt][0] + bq0, acc[0][mt][nt][1] + bq0);
            *(float2*)&g_q[o1] = make_float2(acc[0][mt][nt][2] + bq1, acc[0][mt][nt][3] + bq1);
            *(float2*)&g_k[o0] = make_float2(acc[1][mt][nt][0] + bk0, acc[1][mt][nt][1] + bk0);
            *(float2*)&g_k[o1] = make_float2(acc[1][mt][nt][2] + bk1, acc[1][mt][nt][3] + bk1);
            *(float2*)&g_v[o0] = make_float2(acc[2][mt][nt][0] + bv0, acc[2][mt][nt][1] + bv0);
            *(float2*)&g_v[o1] = make_float2(acc[2][mt][nt][2] + bv1, acc[2][mt][nt][3] + bv1);
        }
    }
}

// =====================================================================
// 2) Patch gather: qs/ks/vs[b, l, d] from q/k/v[bt, ch, pix]
// =====================================================================
__global__ void patch_qkv(int p, int o, int dd, int L, int sBase, float qscale)
{
    const int idx = blockIdx.x * 256 + threadIdx.x;
    const int total = 2 * L * dd;
    if (idx >= total) return;
    const int b   = idx / (L * dd);
    const int rem = idx % (L * dd);
    const int l   = rem / dd;
    const int d   = rem % dd;
    const int t   = l / (o * o);
    const int r2  = l % (o * o);
    const int oy  = r2 / o, ox = r2 % o;
    const int c   = d / (p * p);
    const int r3  = d % (p * p);
    const int py  = r3 / p, px = r3 % p;
    const size_t src = ((size_t)(b * 8 + t) * DCH + (sBase + c)) * HW
                     + (oy * p + py) * 32 + (ox * p + px);
    g_qs[idx] = g_q[src] * qscale;
    g_ks[idx] = g_k[src];
    g_vs[idx] = g_v[src];
}

__global__ void zero_scores(int n)   // n multiple of 4
{
    int i = (blockIdx.x * 256 + threadIdx.x) * 4;
    if (i < n) *(float4*)&g_sc[i] = make_float4(0.f, 0.f, 0.f, 0.f);
}

// =====================================================================
// 3) Scores (tf32 TC, NT): S[b,l,m] = sum_d qs[b,l,d]*ks[b,m,d], split-K opt
// =====================================================================
__global__ void gemm_scores_tc(int L, int dd, int splitK)
{
    const int bz    = blockIdx.z;
    const int batch = bz / splitK;
    const int ksp   = bz % splitK;
    const int kLen  = dd / splitK;
    const float* __restrict__ A = g_qs + (size_t)batch * L * dd;
    const float* __restrict__ B = g_ks + (size_t)batch * L * dd;
    float* C = g_sc + (size_t)batch * L * L;
    const int mBase = blockIdx.y * 64;
    const int nBase = blockIdx.x * 64;

    __shared__ unsigned As[64][20], Bs[64][20];   // both [dim][K] (NT)

    const int tid  = threadIdx.x;           // 128
    const int lane = tid & 31, warp = tid >> 5;
    const int wm = (warp & 1) * 32, wn = (warp >> 1) * 32;
    const int g = lane >> 2, t4 = lane & 3;
    const int rowL = tid >> 1;
    const int offL = (tid & 1) * 8;

    float acc[2][4][4];
    #pragma unroll
    for (int mt = 0; mt < 2; mt++)
        #pragma unroll
        for (int nt = 0; nt < 4; nt++)
            #pragma unroll
            for (int e = 0; e < 4; e++) acc[mt][nt][e] = 0.f;

    const int kBeg = ksp * kLen;
    for (int k0 = kBeg; k0 < kBeg + kLen; k0 += 16) {
        float4 a0 = *(const float4*)&A[(size_t)(mBase + rowL) * dd + k0 + offL];
        float4 a1 = *(const float4*)&A[(size_t)(mBase + rowL) * dd + k0 + offL + 4];
        float4 b0 = *(const float4*)&B[(size_t)(nBase + rowL) * dd + k0 + offL];
        float4 b1 = *(const float4*)&B[(size_t)(nBase + rowL) * dd + k0 + offL + 4];
        __syncthreads();
        *(uint4*)&As[rowL][offL]     = tf4(a0);
        *(uint4*)&As[rowL][offL + 4] = tf4(a1);
        *(uint4*)&Bs[rowL][offL]     = tf4(b0);
        *(uint4*)&Bs[rowL][offL + 4] = tf4(b1);
        __syncthreads();
        #pragma unroll
        for (int kk = 0; kk < 16; kk += 8) {
            unsigned af[2][4], bf[4][2];
            #pragma unroll
            for (int mt = 0; mt < 2; mt++) {
                const int mr = wm + mt * 16 + g;
                af[mt][0] = As[mr][kk + t4];
                af[mt][1] = As[mr + 8][kk + t4];
                af[mt][2] = As[mr][kk + t4 + 4];
                af[mt][3] = As[mr + 8][kk + t4 + 4];
            }
            #pragma unroll
            for (int nt = 0; nt < 4; nt++) {
                bf[nt][0] = Bs[wn + nt * 8 + g][kk + t4];
                bf[nt][1] = Bs[wn + nt * 8 + g][kk + t4 + 4];
            }
            #pragma unroll
            for (int mt = 0; mt < 2; mt++)
                #pragma unroll
                for (int nt = 0; nt < 4; nt++)
                    mma_tf32(acc[mt][nt], af[mt][0], af[mt][1], af[mt][2], af[mt][3],
                             bf[nt][0], bf[nt][1]);
        }
    }

    #pragma unroll
    for (int mt = 0; mt < 2; mt++) {
        const int r0 = mBase + wm + mt * 16 + g;
        #pragma unroll
        for (int nt = 0; nt < 4; nt++) {
            const int c0 = nBase + wn + nt * 8 + 2 * t4;
            if (splitK == 1) {
                *(float2*)&C[(size_t)r0 * L + c0] =
                    make_float2(acc[mt][nt][0], acc[mt][nt][1]);
                *(float2*)&C[(size_t)(r0 + 8) * L + c0] =
                    make_float2(acc[mt][nt][2], acc[mt][nt][3]);
            } else {
                atomicAdd(&C[(size_t)r0 * L + c0],       acc[mt][nt][0]);
                atomicAdd(&C[(size_t)r0 * L + c0 + 1],   acc[mt][nt][1]);
                atomicAdd(&C[(size_t)(r0 + 8) * L + c0],     acc[mt][nt][2]);
                atomicAdd(&C[(size_t)(r0 + 8) * L + c0 + 1], acc[mt][nt][3]);
            }
        }
    }
}

// =====================================================================
// 4) Row softmax over g_sc (smem-cached: 1 gmem read + 1 gmem write)
// =====================================================================
__global__ void softmax_rows(int L)
{
    __shared__ float row[8192];
    __shared__ float red[256];
    float* grow = g_sc + (size_t)blockIdx.x * L;
    const int tid = threadIdx.x;
    const int L4 = L >> 2;

    float m = -1e30f;
    for (int i = tid; i < L4; i += 256) {
        float4 v = *(const float4*)&grow[i * 4];
        *(float4*)&row[i * 4] = v;
        m = fmaxf(fmaxf(m, fmaxf(v.x, v.y)), fmaxf(v.z, v.w));
    }
    red[tid] = m; __syncthreads();
    for (int s = 128; s > 0; s >>= 1) {
        if (tid < s) red[tid] = fmaxf(red[tid], red[tid + s]);
        __syncthreads();
    }
    m = red[0];
    __syncthreads();

    float sum = 0.f;
    for (int i = tid; i < L4; i += 256) {
        float4 v = *(const float4*)&row[i * 4];
        v.x = __expf(v.x - m); v.y = __expf(v.y - m);
        v.z = __expf(v.z - m); v.w = __expf(v.w - m);
        *(float4*)&row[i * 4] = v;
        sum += v.x + v.y + v.z + v.w;
    }
    red[tid] = sum; __syncthreads();
    for (int s = 128; s > 0; s >>= 1) {
        if (tid < s) red[tid] += red[tid + s];
        __syncthreads();
    }
    const float inv = 1.0f / red[0];
    __syncthreads();
    for (int i = tid; i < L4; i += 256) {
        float4 v = *(const float4*)&row[i * 4];
        v.x *= inv; v.y *= inv; v.z *= inv; v.w *= inv;
        *(float4*)&grow[i * 4] = v;
    }
}

// =====================================================================
// 5) P·V (tf32 TC, NN) with fused un-patch scatter into g_att
//    lp = log2(p), lo = log2(o)
// =====================================================================
__global__ void gemm_pv_tc(int L, int dd, int lp, int lo, int sBase)
{
    const int batch = blockIdx.z;
    const float* __restrict__ A = g_sc + (size_t)batch * L * L;    // [L][L]
    const float* __restrict__ B = g_vs + (size_t)batch * L * dd;   // [L(k)][dd]
    const int mBase = blockIdx.y * 64;
    const int nBase = blockIdx.x * 64;

    __shared__ unsigned As[64][20];   // [M][K]
    __shared__ unsigned Bs[16][68];   // [K][N]

    const int tid  = threadIdx.x;
    const int lane = tid & 31, warp = tid >> 5;
    const int wm = (warp & 1) * 32, wn = (warp >> 1) * 32;
    const int g = lane >> 2, t4 = lane & 3;
    const int rowA = tid >> 1, offA = (tid & 1) * 8;
    const int rowB = tid >> 3, offB = (tid & 7) * 8;

    float acc[2][4][4];
    #pragma unroll
    for (int mt = 0; mt < 2; mt++)
        #pragma unroll
        for (int nt = 0; nt < 4; nt++)
            #pragma unroll
            for (int e = 0; e < 4; e++) acc[mt][nt][e] = 0.f;

    for (int k0 = 0; k0 < L; k0 += 16) {
        float4 a0 = *(const float4*)&A[(size_t)(mBase + rowA) * L + k0 + offA];
        float4 a1 = *(const float4*)&A[(size_t)(mBase + rowA) * L + k0 + offA + 4];
        float4 b0 = *(const float4*)&B[(size_t)(k0 + rowB) * dd + nBase + offB];
        float4 b1 = *(const float4*)&B[(size_t)(k0 + rowB) * dd + nBase + offB + 4];
        __syncthreads();
        *(uint4*)&As[rowA][offA]     = tf4(a0);
        *(uint4*)&As[rowA][offA + 4] = tf4(a1);
        *(uint4*)&Bs[rowB][offB]     = tf4(b0);
        *(uint4*)&Bs[rowB][offB + 4] = tf4(b1);
        __syncthreads();
        #pragma unroll
        for (int kk = 0; kk < 16; kk += 8) {
            unsigned af[2][4], bf[4][2];
            #pragma unroll
            for (int mt = 0; mt < 2; mt++) {
                const int mr = wm + mt * 16 + g;
                af[mt][0] = As[mr][kk + t4];
                af[mt][1] = As[mr + 8][kk + t4];
                af[mt][2] = As[mr][kk + t4 + 4];
                af[mt][3] = As[mr + 8][kk + t4 + 4];
            }
            #pragma unroll
            for (int nt = 0; nt < 4; nt++) {
                bf[nt][0] = Bs[kk + t4][wn + nt * 8 + g];
                bf[nt][1] = Bs[kk + t4 + 4][wn + nt * 8 + g];
            }
            #pragma unroll
            for (int mt = 0; mt < 2; mt++)
                #pragma unroll
                for (int nt = 0; nt < 4; nt++)
                    mma_tf32(acc[mt][nt], af[mt][0], af[mt][1], af[mt][2], af[mt][3],
                             bf[nt][0], bf[nt][1]);
        }
    }

    const int oo = 1 << lo, pp = 1 << lp;
    #pragma unroll
    for (int mt = 0; mt < 2; mt++) {
        #pragma unroll
        for (int nt = 0; nt < 4; nt++) {
            #pragma unroll
            for (int e = 0; e < 4; e++) {
                const int l = mBase + wm + mt * 16 + g + (e >= 2 ? 8 : 0);
                const int d = nBase + wn + nt * 8 + 2 * t4 + (e & 1);
                const int t  = l >> (2 * lo);
                const int r2 = l & (oo * oo - 1);
                const int oy = r2 >> lo, ox = r2 & (oo - 1);
                const int c  = d >> (2 * lp);
                const int r3 = d & (pp * pp - 1);
                const int py = r3 >> lp, px = r3 & (pp - 1);
                const size_t dst = ((size_t)(batch * 8 + t) * DCH + sBase + c) * HW
                                 + (size_t)(((oy << lp) + py) * 32 + (ox << lp) + px);
                g_att[dst] = acc[mt][nt][e];
            }
        }
    }
}

// =====================================================================
// 6) 3x3 SAME conv (tf32 TC implicit GEMM, K=2304) + bias + LeakyReLU(0.2)
// =====================================================================
__global__ void conv3_leaky_tc(const float* __restrict__ wo, const float* __restrict__ bo,
                               float* __restrict__ out)
{
    const int bt    = blockIdx.z;
    const int oBase = blockIdx.y * 64;
    const int pBase = blockIdx.x * 64;

    __shared__ unsigned As[64][20];   // [Mout][K]
    __shared__ unsigned Bs[16][68];   // [K][Npix]

    const int tid  = threadIdx.x;
    const int lane = tid & 31, warp = tid >> 5;
    const int wm = (warp & 1) * 32, wn = (warp >> 1) * 32;
    const int g = lane >> 2, t4 = lane & 3;
    const int rowA = tid >> 1, offA = (tid & 1) * 8;
    const int rowB = tid >> 3, offB = (tid & 7) * 8;

    float acc[2][4][4];
    #pragma unroll
    for (int mt = 0; mt < 2; mt++)
        #pragma unroll
        for (int nt = 0; nt < 4; nt++)
            #pragma unroll
            for (int e = 0; e < 4; e++) acc[mt][nt][e] = 0.f;

    const float* inb = g_att + (size_t)bt * CHW;

    for (int k0 = 0; k0 < 2304; k0 += 16) {
        float4 a0 = *(const float4*)&wo[(size_t)(oBase + rowA) * 2304 + k0 + offA];
        float4 a1 = *(const float4*)&wo[(size_t)(oBase + rowA) * 2304 + k0 + offA + 4];
        const int k  = k0 + rowB;
        const int ic = k / 9;
        const int r  = k % 9;
        const int ky = r / 3 - 1, kx = r % 3 - 1;
        float bv[8];
        #pragma unroll
        for (int q = 0; q < 8; q++) {
            const int ppix = pBase + offB + q;
            const int y  = (ppix >> 5) + ky;
            const int xx = (ppix & 31) + kx;
            bv[q] = (y >= 0 && y < 32 && xx >= 0 && xx < 32)
                  ? inb[(size_t)ic * HW + y * 32 + xx] : 0.f;
        }
        __syncthreads();
        *(uint4*)&As[rowA][offA]     = tf4(a0);
        *(uint4*)&As[rowA][offA + 4] = tf4(a1);
        #pragma unroll
        for (int q = 0; q < 8; q++) Bs[rowB][offB + q] = f2tf(bv[q]);
        __syncthreads();
        #pragma unroll
        for (int kk = 0; kk < 16; kk += 8) {
            unsigned af[2][4], bf[4][2];
            #pragma unroll
            for (int mt = 0; mt < 2; mt++) {
                const int mr = wm + mt * 16 + g;
                af[mt][0] = As[mr][kk + t4];
                af[mt][1] = As[mr + 8][kk + t4];
                af[mt][2] = As[mr][kk + t4 + 4];
                af[mt][3] = As[mr + 8][kk + t4 + 4];
            }
            #pragma unroll
            for (int nt = 0; nt < 4; nt++) {
                bf[nt][0] = Bs[kk + t4][wn + nt * 8 + g];
                bf[nt][1] = Bs[kk + t4 + 4][wn + nt * 8 + g];
            }
            #pragma unroll
            for (int mt = 0; mt < 2; mt++)
                #pragma unroll
                for (int nt = 0; nt < 4; nt++)
                    mma_tf32(acc[mt][nt], af[mt][0], af[mt][1], af[mt][2], af[mt][3],
                             bf[nt][0], bf[nt][1]);
        }
    }

    #pragma unroll
    for (int mt = 0; mt < 2; mt++) {
        const int r0 = oBase + wm + mt * 16 + g;
        const float bi0 = bo[r0], bi1 = bo[r0 + 8];
        #pragma unroll
        for (int nt = 0; nt < 4; nt++) {
            const int c0 = pBase + wn + nt * 8 + 2 * t4;
            float v0 = acc[mt][nt][0] + bi0;
            float v1 = acc[mt][nt][1] + bi0;
            float v2 = acc[mt][nt][2] + bi1;
            float v3 = acc[mt][nt][3] + bi1;
            v0 = (v0 > 0.f) ? v0 : 0.2f * v0;
            v1 = (v1 > 0.f) ? v1 : 0.2f * v1;
            v2 = (v2 > 0.f) ? v2 : 0.2f * v2;
            v3 = (v3 > 0.f) ? v3 : 0.2f * v3;
            *(float2*)&out[(size_t)bt * CHW + (size_t)r0 * HW + c0] = make_float2(v0, v1);
            *(float2*)&out[(size_t)bt * CHW + (size_t)(r0 + 8) * HW + c0] = make_float2(v2, v3);
        }
    }
}

// =====================================================================
// Launch
// =====================================================================
extern "C" void kernel_launch(void* const* d_in, const int* in_sizes, int n_in,
                              void* d_out, int out_size)
{
    (void)in_sizes; (void)n_in; (void)out_size;
    const float* x  = (const float*)d_in[0];
    // d_in[1] = m : dead code in the reference (masked_fill result discarded)
    const float* wq = (const float*)d_in[2];
    const float* bq = (const float*)d_in[3];
    const float* wk = (const float*)d_in[4];
    const float* bk = (const float*)d_in[5];
    const float* wv = (const float*)d_in[6];
    const float* bv = (const float*)d_in[7];
    const float* wo = (const float*)d_in[8];
    const float* bo = (const float*)d_in[9];
    float* out = (float*)d_out;

    qkv_proj_tc<<<dim3(16, 4, 16), 128>>>(x, wq, bq, wk, bk, wv, bv);

    struct ScaleCfg { int p, o, lp, lo, dd, L, sBase, splitK; };
    const ScaleCfg cfgs[4] = {
        {8,  4, 3, 2, 4096,  128,   0, 32},
        {4,  8, 2, 3, 1024,  512,  64, 16},
        {2, 16, 1, 4,  256, 2048, 128,  1},
        {1, 32, 0, 5,   64, 8192, 192,  1},
    };

    for (int s = 0; s < 4; s++) {
        const ScaleCfg c = cfgs[s];
        const int total = 2 * c.L * c.dd;
        const float qscale = 1.0f / sqrtf((float)c.dd);
        patch_qkv<<<(total + 255) / 256, 256>>>(c.p, c.o, c.dd, c.L, c.sBase, qscale);
        if (c.splitK > 1) {
            const int n = 2 * c.L * c.L;
            zero_scores<<<(n / 4 + 255) / 256, 256>>>(n);
        }
        gemm_scores_tc<<<dim3(c.L / 64, c.L / 64, 2 * c.splitK), 128>>>(c.L, c.dd, c.splitK);
        softmax_rows<<<2 * c.L, 256>>>(c.L);
        gemm_pv_tc<<<dim3(c.dd / 64, c.L / 64, 2), 128>>>(c.L, c.dd, c.lp, c.lo, c.sBase);
    }

    conv3_leaky_tc<<<dim3(16, 4, 16), 128>>>(wo, bo, out);
}

// round 4
// speedup vs baseline: 2.2649x; 1.4789x over previous
#include <cuda_runtime.h>
#include <math.h>

// Problem constants (fixed shapes from the reference)
#define BT   16          // B*T
#define DCH  256         // channels D
#define HW   1024        // 32*32
#define CHW  (DCH*HW)    // 262144

// ---------------- static scratch ----------------
__device__ float g_q[BT * CHW];
__device__ float g_k[BT * CHW];
__device__ float g_v[BT * CHW];
__device__ float g_qs[2 * 524288];   // [b, L, dd] ; L*dd == 524288 for every scale
__device__ float g_ks[2 * 524288];
__device__ float g_vs[2 * 524288];
__device__ float g_att[BT * CHW];    // concat of per-scale attention outputs
__device__ float g_sc[2ll * 2048 * 2048];  // scores scratch (scales 0-2 only now)

// ---------------- tf32 mma helpers ----------------
__device__ __forceinline__ unsigned f2tf(float f) {
    unsigned u;
    asm("cvt.rna.tf32.f32 %0, %1;" : "=r"(u) : "f"(f));
    return u;
}

__device__ __forceinline__ void mma_tf32(float c[4],
                                         unsigned a0, unsigned a1, unsigned a2, unsigned a3,
                                         unsigned b0, unsigned b1)
{
    asm volatile(
        "mma.sync.aligned.m16n8k8.row.col.f32.tf32.tf32.f32 "
        "{%0,%1,%2,%3}, {%4,%5,%6,%7}, {%8,%9}, {%0,%1,%2,%3};"
        : "+f"(c[0]), "+f"(c[1]), "+f"(c[2]), "+f"(c[3])
        : "r"(a0), "r"(a1), "r"(a2), "r"(a3), "r"(b0), "r"(b1));
}

__device__ __forceinline__ uint4 tf4(float4 v) {
    uint4 u;
    u.x = f2tf(v.x); u.y = f2tf(v.y); u.z = f2tf(v.z); u.w = f2tf(v.w);
    return u;
}

// =====================================================================
// 1) Fused QKV projection (tf32 TC)
// =====================================================================
__global__ void qkv_proj_tc(const float* __restrict__ x,
                            const float* __restrict__ wq, const float* __restrict__ bq,
                            const float* __restrict__ wk, const float* __restrict__ bk,
                            const float* __restrict__ wv, const float* __restrict__ bv)
{
    const int bt    = blockIdx.z;
    const int oBase = blockIdx.y * 64;
    const int pBase = blockIdx.x * 64;

    __shared__ unsigned Aq[64][20], Ak[64][20], Av[64][20];
    __shared__ unsigned Bs[16][68];

    const int tid  = threadIdx.x;
    const int lane = tid & 31, warp = tid >> 5;
    const int wm = (warp & 1) * 32, wn = (warp >> 1) * 32;
    const int g = lane >> 2, t4 = lane & 3;

    const int rowA = tid >> 1;
    const int offA = (tid & 1) * 8;
    const int rowB = tid >> 3;
    const int offB = (tid & 7) * 8;

    float acc[3][2][4][4];
    #pragma unroll
    for (int s = 0; s < 3; s++)
        #pragma unroll
        for (int mt = 0; mt < 2; mt++)
            #pragma unroll
            for (int nt = 0; nt < 4; nt++)
                #pragma unroll
                for (int e = 0; e < 4; e++) acc[s][mt][nt][e] = 0.f;

    const float* xb = x + (size_t)bt * CHW;

    for (int k0 = 0; k0 < 256; k0 += 16) {
        float4 q0 = *(const float4*)&wq[(oBase + rowA) * 256 + k0 + offA];
        float4 q1 = *(const float4*)&wq[(oBase + rowA) * 256 + k0 + offA + 4];
        float4 k0v = *(const float4*)&wk[(oBase + rowA) * 256 + k0 + offA];
        float4 k1v = *(const float4*)&wk[(oBase + rowA) * 256 + k0 + offA + 4];
        float4 v0 = *(const float4*)&wv[(oBase + rowA) * 256 + k0 + offA];
        float4 v1 = *(const float4*)&wv[(oBase + rowA) * 256 + k0 + offA + 4];
        float4 b0 = *(const float4*)&xb[(size_t)(k0 + rowB) * HW + pBase + offB];
        float4 b1 = *(const float4*)&xb[(size_t)(k0 + rowB) * HW + pBase + offB + 4];
        __syncthreads();
        *(uint4*)&Aq[rowA][offA]     = tf4(q0);
        *(uint4*)&Aq[rowA][offA + 4] = tf4(q1);
        *(uint4*)&Ak[rowA][offA]     = tf4(k0v);
        *(uint4*)&Ak[rowA][offA + 4] = tf4(k1v);
        *(uint4*)&Av[rowA][offA]     = tf4(v0);
        *(uint4*)&Av[rowA][offA + 4] = tf4(v1);
        *(uint4*)&Bs[rowB][offB]     = tf4(b0);
        *(uint4*)&Bs[rowB][offB + 4] = tf4(b1);
        __syncthreads();
        #pragma unroll
        for (int kk = 0; kk < 16; kk += 8) {
            unsigned bf[4][2];
            #pragma unroll
            for (int nt = 0; nt < 4; nt++) {
                bf[nt][0] = Bs[kk + t4][wn + nt * 8 + g];
                bf[nt][1] = Bs[kk + t4 + 4][wn + nt * 8 + g];
            }
            #pragma unroll
            for (int mt = 0; mt < 2; mt++) {
                const int mr = wm + mt * 16 + g;
                unsigned aq0 = Aq[mr][kk + t4],     aq1 = Aq[mr + 8][kk + t4];
                unsigned aq2 = Aq[mr][kk + t4 + 4], aq3 = Aq[mr + 8][kk + t4 + 4];
                unsigned ak0 = Ak[mr][kk + t4],     ak1 = Ak[mr + 8][kk + t4];
                unsigned ak2 = Ak[mr][kk + t4 + 4], ak3 = Ak[mr + 8][kk + t4 + 4];
                unsigned av0 = Av[mr][kk + t4],     av1 = Av[mr + 8][kk + t4];
                unsigned av2 = Av[mr][kk + t4 + 4], av3 = Av[mr + 8][kk + t4 + 4];
                #pragma unroll
                for (int nt = 0; nt < 4; nt++) {
                    mma_tf32(acc[0][mt][nt], aq0, aq1, aq2, aq3, bf[nt][0], bf[nt][1]);
                    mma_tf32(acc[1][mt][nt], ak0, ak1, ak2, ak3, bf[nt][0], bf[nt][1]);
                    mma_tf32(acc[2][mt][nt], av0, av1, av2, av3, bf[nt][0], bf[nt][1]);
                }
            }
        }
    }

    #pragma unroll
    for (int mt = 0; mt < 2; mt++) {
        const int r0 = oBase + wm + mt * 16 + g;
        const float bq0 = bq[r0], bq1 = bq[r0 + 8];
        const float bk0 = bk[r0], bk1 = bk[r0 + 8];
        const float bv0 = bv[r0], bv1 = bv[r0 + 8];
        #pragma unroll
        for (int nt = 0; nt < 4; nt++) {
            const int c0 = pBase + wn + nt * 8 + 2 * t4;
            const size_t o0 = (size_t)bt * CHW + (size_t)r0 * HW + c0;
            const size_t o1 = (size_t)bt * CHW + (size_t)(r0 + 8) * HW + c0;
            *(float2*)&g_q[o0] = make_float2(acc[0][mt][nt][0] + bq0, acc[0][mt][nt][1] + bq0);
            *(float2*)&g_q[o1] = make_float2(acc[0][mt][nt][2] + bq1, acc[0][mt][nt][3] + bq1);
            *(float2*)&g_k[o0] = make_float2(acc[1][mt][nt][0] + bk0, acc[1][mt][nt][1] + bk0);
            *(float2*)&g_k[o1] = make_float2(acc[1][mt][nt][2] + bk1, acc[1][mt][nt][3] + bk1);
            *(float2*)&g_v[o0] = make_float2(acc[2][mt][nt][0] + bv0, acc[2][mt][nt][1] + bv0);
            *(float2*)&g_v[o1] = make_float2(acc[2][mt][nt][2] + bv1, acc[2][mt][nt][3] + bv1);
        }
    }
}

// =====================================================================
// 2) Patch gather
// =====================================================================
__global__ void patch_qkv(int p, int o, int dd, int L, int sBase, float qscale)
{
    const int idx = blockIdx.x * 256 + threadIdx.x;
    const int total = 2 * L * dd;
    if (idx >= total) return;
    const int b   = idx / (L * dd);
    const int rem = idx % (L * dd);
    const int l   = rem / dd;
    const int d   = rem % dd;
    const int t   = l / (o * o);
    const int r2  = l % (o * o);
    const int oy  = r2 / o, ox = r2 % o;
    const int c   = d / (p * p);
    const int r3  = d % (p * p);
    const int py  = r3 / p, px = r3 % p;
    const size_t src = ((size_t)(b * 8 + t) * DCH + (sBase + c)) * HW
                     + (oy * p + py) * 32 + (ox * p + px);
    g_qs[idx] = g_q[src] * qscale;
    g_ks[idx] = g_k[src];
    g_vs[idx] = g_v[src];
}

__global__ void zero_scores(int n)
{
    int i = (blockIdx.x * 256 + threadIdx.x) * 4;
    if (i < n) *(float4*)&g_sc[i] = make_float4(0.f, 0.f, 0.f, 0.f);
}

// =====================================================================
// 3) Scores (tf32 TC, NT) for scales 0-2
// =====================================================================
__global__ void gemm_scores_tc(int L, int dd, int splitK)
{
    const int bz    = blockIdx.z;
    const int batch = bz / splitK;
    const int ksp   = bz % splitK;
    const int kLen  = dd / splitK;
    const float* __restrict__ A = g_qs + (size_t)batch * L * dd;
    const float* __restrict__ B = g_ks + (size_t)batch * L * dd;
    float* C = g_sc + (size_t)batch * L * L;
    const int mBase = blockIdx.y * 64;
    const int nBase = blockIdx.x * 64;

    __shared__ unsigned As[64][20], Bs[64][20];

    const int tid  = threadIdx.x;
    const int lane = tid & 31, warp = tid >> 5;
    const int wm = (warp & 1) * 32, wn = (warp >> 1) * 32;
    const int g = lane >> 2, t4 = lane & 3;
    const int rowL = tid >> 1;
    const int offL = (tid & 1) * 8;

    float acc[2][4][4];
    #pragma unroll
    for (int mt = 0; mt < 2; mt++)
        #pragma unroll
        for (int nt = 0; nt < 4; nt++)
            #pragma unroll
            for (int e = 0; e < 4; e++) acc[mt][nt][e] = 0.f;

    const int kBeg = ksp * kLen;
    for (int k0 = kBeg; k0 < kBeg + kLen; k0 += 16) {
        float4 a0 = *(const float4*)&A[(size_t)(mBase + rowL) * dd + k0 + offL];
        float4 a1 = *(const float4*)&A[(size_t)(mBase + rowL) * dd + k0 + offL + 4];
        float4 b0 = *(const float4*)&B[(size_t)(nBase + rowL) * dd + k0 + offL];
        float4 b1 = *(const float4*)&B[(size_t)(nBase + rowL) * dd + k0 + offL + 4];
        __syncthreads();
        *(uint4*)&As[rowL][offL]     = tf4(a0);
        *(uint4*)&As[rowL][offL + 4] = tf4(a1);
        *(uint4*)&Bs[rowL][offL]     = tf4(b0);
        *(uint4*)&Bs[rowL][offL + 4] = tf4(b1);
        __syncthreads();
        #pragma unroll
        for (int kk = 0; kk < 16; kk += 8) {
            unsigned af[2][4], bf[4][2];
            #pragma unroll
            for (int mt = 0; mt < 2; mt++) {
                const int mr = wm + mt * 16 + g;
                af[mt][0] = As[mr][kk + t4];
                af[mt][1] = As[mr + 8][kk + t4];
                af[mt][2] = As[mr][kk + t4 + 4];
                af[mt][3] = As[mr + 8][kk + t4 + 4];
            }
            #pragma unroll
            for (int nt = 0; nt < 4; nt++) {
                bf[nt][0] = Bs[wn + nt * 8 + g][kk + t4];
                bf[nt][1] = Bs[wn + nt * 8 + g][kk + t4 + 4];
            }
            #pragma unroll
            for (int mt = 0; mt < 2; mt++)
                #pragma unroll
                for (int nt = 0; nt < 4; nt++)
                    mma_tf32(acc[mt][nt], af[mt][0], af[mt][1], af[mt][2], af[mt][3],
                             bf[nt][0], bf[nt][1]);
        }
    }

    #pragma unroll
    for (int mt = 0; mt < 2; mt++) {
        const int r0 = mBase + wm + mt * 16 + g;
        #pragma unroll
        for (int nt = 0; nt < 4; nt++) {
            const int c0 = nBase + wn + nt * 8 + 2 * t4;
            if (splitK == 1) {
                *(float2*)&C[(size_t)r0 * L + c0] =
                    make_float2(acc[mt][nt][0], acc[mt][nt][1]);
                *(float2*)&C[(size_t)(r0 + 8) * L + c0] =
                    make_float2(acc[mt][nt][2], acc[mt][nt][3]);
            } else {
                atomicAdd(&C[(size_t)r0 * L + c0],       acc[mt][nt][0]);
                atomicAdd(&C[(size_t)r0 * L + c0 + 1],   acc[mt][nt][1]);
                atomicAdd(&C[(size_t)(r0 + 8) * L + c0],     acc[mt][nt][2]);
                atomicAdd(&C[(size_t)(r0 + 8) * L + c0 + 1], acc[mt][nt][3]);
            }
        }
    }
}

// =====================================================================
// 4) Row softmax (scales 0-2, L<=2048)
// =====================================================================
__global__ void softmax_rows(int L)
{
    __shared__ float row[2048];
    __shared__ float red[256];
    float* grow = g_sc + (size_t)blockIdx.x * L;
    const int tid = threadIdx.x;
    const int L4 = L >> 2;

    float m = -1e30f;
    for (int i = tid; i < L4; i += 256) {
        float4 v = *(const float4*)&grow[i * 4];
        *(float4*)&row[i * 4] = v;
        m = fmaxf(fmaxf(m, fmaxf(v.x, v.y)), fmaxf(v.z, v.w));
    }
    red[tid] = m; __syncthreads();
    for (int s = 128; s > 0; s >>= 1) {
        if (tid < s) red[tid] = fmaxf(red[tid], red[tid + s]);
        __syncthreads();
    }
    m = red[0];
    __syncthreads();

    float sum = 0.f;
    for (int i = tid; i < L4; i += 256) {
        float4 v = *(const float4*)&row[i * 4];
        v.x = __expf(v.x - m); v.y = __expf(v.y - m);
        v.z = __expf(v.z - m); v.w = __expf(v.w - m);
        *(float4*)&row[i * 4] = v;
        sum += v.x + v.y + v.z + v.w;
    }
    red[tid] = sum; __syncthreads();
    for (int s = 128; s > 0; s >>= 1) {
        if (tid < s) red[tid] += red[tid + s];
        __syncthreads();
    }
    const float inv = 1.0f / red[0];
    __syncthreads();
    for (int i = tid; i < L4; i += 256) {
        float4 v = *(const float4*)&row[i * 4];
        v.x *= inv; v.y *= inv; v.z *= inv; v.w *= inv;
        *(float4*)&grow[i * 4] = v;
    }
}

// =====================================================================
// 5) P·V (tf32 TC, NN) with fused un-patch scatter (scales 0-2)
// =====================================================================
__global__ void gemm_pv_tc(int L, int dd, int lp, int lo, int sBase)
{
    const int batch = blockIdx.z;
    const float* __restrict__ A = g_sc + (size_t)batch * L * L;
    const float* __restrict__ B = g_vs + (size_t)batch * L * dd;
    const int mBase = blockIdx.y * 64;
    const int nBase = blockIdx.x * 64;

    __shared__ unsigned As[64][20];
    __shared__ unsigned Bs[16][68];

    const int tid  = threadIdx.x;
    const int lane = tid & 31, warp = tid >> 5;
    const int wm = (warp & 1) * 32, wn = (warp >> 1) * 32;
    const int g = lane >> 2, t4 = lane & 3;
    const int rowA = tid >> 1, offA = (tid & 1) * 8;
    const int rowB = tid >> 3, offB = (tid & 7) * 8;

    float acc[2][4][4];
    #pragma unroll
    for (int mt = 0; mt < 2; mt++)
        #pragma unroll
        for (int nt = 0; nt < 4; nt++)
            #pragma unroll
            for (int e = 0; e < 4; e++) acc[mt][nt][e] = 0.f;

    for (int k0 = 0; k0 < L; k0 += 16) {
        float4 a0 = *(const float4*)&A[(size_t)(mBase + rowA) * L + k0 + offA];
        float4 a1 = *(const float4*)&A[(size_t)(mBase + rowA) * L + k0 + offA + 4];
        float4 b0 = *(const float4*)&B[(size_t)(k0 + rowB) * dd + nBase + offB];
        float4 b1 = *(const float4*)&B[(size_t)(k0 + rowB) * dd + nBase + offB + 4];
        __syncthreads();
        *(uint4*)&As[rowA][offA]     = tf4(a0);
        *(uint4*)&As[rowA][offA + 4] = tf4(a1);
        *(uint4*)&Bs[rowB][offB]     = tf4(b0);
        *(uint4*)&Bs[rowB][offB + 4] = tf4(b1);
        __syncthreads();
        #pragma unroll
        for (int kk = 0; kk < 16; kk += 8) {
            unsigned af[2][4], bf[4][2];
            #pragma unroll
            for (int mt = 0; mt < 2; mt++) {
                const int mr = wm + mt * 16 + g;
                af[mt][0] = As[mr][kk + t4];
                af[mt][1] = As[mr + 8][kk + t4];
                af[mt][2] = As[mr][kk + t4 + 4];
                af[mt][3] = As[mr + 8][kk + t4 + 4];
            }
            #pragma unroll
            for (int nt = 0; nt < 4; nt++) {
                bf[nt][0] = Bs[kk + t4][wn + nt * 8 + g];
                bf[nt][1] = Bs[kk + t4 + 4][wn + nt * 8 + g];
            }
            #pragma unroll
            for (int mt = 0; mt < 2; mt++)
                #pragma unroll
                for (int nt = 0; nt < 4; nt++)
                    mma_tf32(acc[mt][nt], af[mt][0], af[mt][1], af[mt][2], af[mt][3],
                             bf[nt][0], bf[nt][1]);
        }
    }

    const int oo = 1 << lo, pp = 1 << lp;
    #pragma unroll
    for (int mt = 0; mt < 2; mt++) {
        #pragma unroll
        for (int nt = 0; nt < 4; nt++) {
            #pragma unroll
            for (int e = 0; e < 4; e++) {
                const int l = mBase + wm + mt * 16 + g + (e >= 2 ? 8 : 0);
                const int d = nBase + wn + nt * 8 + 2 * t4 + (e & 1);
                const int t  = l >> (2 * lo);
                const int r2 = l & (oo * oo - 1);
                const int oy = r2 >> lo, ox = r2 & (oo - 1);
                const int c  = d >> (2 * lp);
                const int r3 = d & (pp * pp - 1);
                const int py = r3 >> lp, px = r3 & (pp - 1);
                const size_t dst = ((size_t)(batch * 8 + t) * DCH + sBase + c) * HW
                                 + (size_t)(((oy << lp) + py) * 32 + (ox << lp) + px);
                g_att[dst] = acc[mt][nt][e];
            }
        }
    }
}

// =====================================================================
// 5b) Flash attention for scale 3 (L=8192, dd=64, p=1, o=32, sBase=192)
//     grid (128, 2), 128 threads (4 warps). BM=64 q rows, BN=64 k cols/iter.
//     Dynamic smem: Qs[64][68] | Ks[64][68] | Vs[64][68] | Ps[4][16][68]
// =====================================================================
#define F3_STRIDE 68
#define F3_SMEM_BYTES ((3 * 64 * F3_STRIDE + 4 * 16 * F3_STRIDE) * 4)  // 69632
__global__ void flash3()
{
    extern __shared__ unsigned sm[];
    unsigned* Qs = sm;                       // [64][68]
    unsigned* Ks = sm + 64 * F3_STRIDE;      // [64][68]
    unsigned* Vs = sm + 2 * 64 * F3_STRIDE;  // [64][68]
    unsigned* Ps = sm + 3 * 64 * F3_STRIDE;  // [4][16][68]

    const int batch = blockIdx.y;
    const int qBase = blockIdx.x * 64;
    const int tid  = threadIdx.x;
    const int lane = tid & 31, warp = tid >> 5;
    const int g = lane >> 2, t4 = lane & 3;
    const int wr = warp * 16;
    unsigned* Pw = Ps + warp * 16 * F3_STRIDE;

    const size_t base = (size_t)batch * 524288;   // L*dd = 8192*64

    // Load Q block (qscale already applied in patch_qkv)
    for (int i = tid; i < 1024; i += 128) {
        const int r = i >> 4, c4 = (i & 15) * 4;
        float4 v = *(const float4*)&g_qs[base + (size_t)(qBase + r) * 64 + c4];
        *(uint4*)&Qs[r * F3_STRIDE + c4] = tf4(v);
    }

    float oacc[8][4];
    #pragma unroll
    for (int nt = 0; nt < 8; nt++)
        #pragma unroll
        for (int e = 0; e < 4; e++) oacc[nt][e] = 0.f;
    float m0 = -1e30f, m1 = -1e30f, l0 = 0.f, l1 = 0.f;

    for (int kt = 0; kt < 128; kt++) {
        const int kBase = kt * 64;
        __syncthreads();
        for (int i = tid; i < 1024; i += 128) {
            const int r = i >> 4, c4 = (i & 15) * 4;
            float4 kv = *(const float4*)&g_ks[base + (size_t)(kBase + r) * 64 + c4];
            float4 vv = *(const float4*)&g_vs[base + (size_t)(kBase + r) * 64 + c4];
            *(uint4*)&Ks[r * F3_STRIDE + c4] = tf4(kv);
            *(uint4*)&Vs[r * F3_STRIDE + c4] = tf4(vv);
        }
        __syncthreads();

        // S = Q K^T  (64x64, NT)
        float sacc[8][4];
        #pragma unroll
        for (int nt = 0; nt < 8; nt++)
            #pragma unroll
            for (int e = 0; e < 4; e++) sacc[nt][e] = 0.f;
        #pragma unroll
        for (int kk = 0; kk < 64; kk += 8) {
            const unsigned a0 = Qs[(wr + g) * F3_STRIDE + kk + t4];
            const unsigned a1 = Qs[(wr + g + 8) * F3_STRIDE + kk + t4];
            const unsigned a2 = Qs[(wr + g) * F3_STRIDE + kk + t4 + 4];
            const unsigned a3 = Qs[(wr + g + 8) * F3_STRIDE + kk + t4 + 4];
            #pragma unroll
            for (int nt = 0; nt < 8; nt++) {
                const unsigned b0 = Ks[(nt * 8 + g) * F3_STRIDE + kk + t4];
                const unsigned b1 = Ks[(nt * 8 + g) * F3_STRIDE + kk + t4 + 4];
                mma_tf32(sacc[nt], a0, a1, a2, a3, b0, b1);
            }
        }

        // online softmax
        float rm0 = -1e30f, rm1 = -1e30f;
        #pragma unroll
        for (int nt = 0; nt < 8; nt++) {
            rm0 = fmaxf(rm0, fmaxf(sacc[nt][0], sacc[nt][1]));
            rm1 = fmaxf(rm1, fmaxf(sacc[nt][2], sacc[nt][3]));
        }
        rm0 = fmaxf(rm0, __shfl_xor_sync(0xffffffff, rm0, 1));
        rm0 = fmaxf(rm0, __shfl_xor_sync(0xffffffff, rm0, 2));
        rm1 = fmaxf(rm1, __shfl_xor_sync(0xffffffff, rm1, 1));
        rm1 = fmaxf(rm1, __shfl_xor_sync(0xffffffff, rm1, 2));

        const float mn0 = fmaxf(m0, rm0);
        const float mn1 = fmaxf(m1, rm1);
        const float al0 = __expf(m0 - mn0);
        const float al1 = __expf(m1 - mn1);
        m0 = mn0; m1 = mn1;

        float ps0 = 0.f, ps1 = 0.f;
        #pragma unroll
        for (int nt = 0; nt < 8; nt++) {
            const float p0 = __expf(sacc[nt][0] - mn0);
            const float p1 = __expf(sacc[nt][1] - mn0);
            const float p2 = __expf(sacc[nt][2] - mn1);
            const float p3 = __expf(sacc[nt][3] - mn1);
            ps0 += p0 + p1; ps1 += p2 + p3;
            const int c = nt * 8 + 2 * t4;
            Pw[g * F3_STRIDE + c]           = f2tf(p0);
            Pw[g * F3_STRIDE + c + 1]       = f2tf(p1);
            Pw[(g + 8) * F3_STRIDE + c]     = f2tf(p2);
            Pw[(g + 8) * F3_STRIDE + c + 1] = f2tf(p3);
        }
        ps0 += __shfl_xor_sync(0xffffffff, ps0, 1);
        ps0 += __shfl_xor_sync(0xffffffff, ps0, 2);
        ps1 += __shfl_xor_sync(0xffffffff, ps1, 1);
        ps1 += __shfl_xor_sync(0xffffffff, ps1, 2);
        l0 = l0 * al0 + ps0;
        l1 = l1 * al1 + ps1;

        #pragma unroll
        for (int nt = 0; nt < 8; nt++) {
            oacc[nt][0] *= al0; oacc[nt][1] *= al0;
            oacc[nt][2] *= al1; oacc[nt][3] *= al1;
        }
        __syncwarp();

        // O += P V   (64x64 NN, per-warp P tile)
        #pragma unroll
        for (int kk = 0; kk < 64; kk += 8) {
            const unsigned a0 = Pw[g * F3_STRIDE + kk + t4];
            const unsigned a1 = Pw[(g + 8) * F3_STRIDE + kk + t4];
            const unsigned a2 = Pw[g * F3_STRIDE + kk + t4 + 4];
            const unsigned a3 = Pw[(g + 8) * F3_STRIDE + kk + t4 + 4];
            #pragma unroll
            for (int nt = 0; nt < 8; nt++) {
                const unsigned b0 = Vs[(kk + t4) * F3_STRIDE + nt * 8 + g];
                const unsigned b1 = Vs[(kk + t4 + 4) * F3_STRIDE + nt * 8 + g];
                mma_tf32(oacc[nt], a0, a1, a2, a3, b0, b1);
            }
        }
    }

    // epilogue: normalize + scatter to g_att (p=1: d -> channel 192+d, l -> pixel)
    const float inv0 = 1.0f / l0;
    const float inv1 = 1.0f / l1;
    const int row0 = qBase + wr + g;
    const int row1 = row0 + 8;
    const size_t bt0 = (size_t)(batch * 8 + (row0 >> 10)) * CHW;
    const size_t bt1 = (size_t)(batch * 8 + (row1 >> 10)) * CHW;
    const int px0 = row0 & 1023, px1 = row1 & 1023;
    #pragma unroll
    for (int nt = 0; nt < 8; nt++) {
        const int d = nt * 8 + 2 * t4;
        g_att[bt0 + (size_t)(192 + d) * HW + px0]     = oacc[nt][0] * inv0;
        g_att[bt0 + (size_t)(192 + d + 1) * HW + px0] = oacc[nt][1] * inv0;
        g_att[bt1 + (size_t)(192 + d) * HW + px1]     = oacc[nt][2] * inv1;
        g_att[bt1 + (size_t)(192 + d + 1) * HW + px1] = oacc[nt][3] * inv1;
    }
}

// =====================================================================
// 6) 3x3 SAME conv (tf32 TC implicit GEMM) + bias + LeakyReLU(0.2)
// =====================================================================
__global__ void conv3_leaky_tc(const float* __restrict__ wo, const float* __restrict__ bo,
                               float* __restrict__ out)
{
    const int bt    = blockIdx.z;
    const int oBase = blockIdx.y * 64;
    const int pBase = blockIdx.x * 64;

    __shared__ unsigned As[64][20];
    __shared__ unsigned Bs[16][68];

    const int tid  = threadIdx.x;
    const int lane = tid & 31, warp = tid >> 5;
    const int wm = (warp & 1) * 32, wn = (warp >> 1) * 32;
    const int g = lane >> 2, t4 = lane & 3;
    const int rowA = tid >> 1, offA = (tid & 1) * 8;
    const int rowB = tid >> 3, offB = (tid & 7) * 8;

    float acc[2][4][4];
    #pragma unroll
    for (int mt = 0; mt < 2; mt++)
        #pragma unroll
        for (int nt = 0; nt < 4; nt++)
            #pragma unroll
            for (int e = 0; e < 4; e++) acc[mt][nt][e] = 0.f;

    const float* inb = g_att + (size_t)bt * CHW;

    for (int k0 = 0; k0 < 2304; k0 += 16) {
        float4 a0 = *(const float4*)&wo[(size_t)(oBase + rowA) * 2304 + k0 + offA];
        float4 a1 = *(const float4*)&wo[(size_t)(oBase + rowA) * 2304 + k0 + offA + 4];
        const int k  = k0 + rowB;
        const int ic = k / 9;
        const int r  = k % 9;
        const int ky = r / 3 - 1, kx = r % 3 - 1;
        float bv[8];
        #pragma unroll
        for (int q = 0; q < 8; q++) {
            const int ppix = pBase + offB + q;
            const int y  = (ppix >> 5) + ky;
            const int xx = (ppix & 31) + kx;
            bv[q] = (y >= 0 && y < 32 && xx >= 0 && xx < 32)
                  ? inb[(size_t)ic * HW + y * 32 + xx] : 0.f;
        }
        __syncthreads();
        *(uint4*)&As[rowA][offA]     = tf4(a0);
        *(uint4*)&As[rowA][offA + 4] = tf4(a1);
        #pragma unroll
        for (int q = 0; q < 8; q++) Bs[rowB][offB + q] = f2tf(bv[q]);
        __syncthreads();
        #pragma unroll
        for (int kk = 0; kk < 16; kk += 8) {
            unsigned af[2][4], bf[4][2];
            #pragma unroll
            for (int mt = 0; mt < 2; mt++) {
                const int mr = wm + mt * 16 + g;
                af[mt][0] = As[mr][kk + t4];
                af[mt][1] = As[mr + 8][kk + t4];
                af[mt][2] = As[mr][kk + t4 + 4];
                af[mt][3] = As[mr + 8][kk + t4 + 4];
            }
            #pragma unroll
            for (int nt = 0; nt < 4; nt++) {
                bf[nt][0] = Bs[kk + t4][wn + nt * 8 + g];
                bf[nt][1] = Bs[kk + t4 + 4][wn + nt * 8 + g];
            }
            #pragma unroll
            for (int mt = 0; mt < 2; mt++)
                #pragma unroll
                for (int nt = 0; nt < 4; nt++)
                    mma_tf32(acc[mt][nt], af[mt][0], af[mt][1], af[mt][2], af[mt][3],
                             bf[nt][0], bf[nt][1]);
        }
    }

    #pragma unroll
    for (int mt = 0; mt < 2; mt++) {
        const int r0 = oBase + wm + mt * 16 + g;
        const float bi0 = bo[r0], bi1 = bo[r0 + 8];
        #pragma unroll
        for (int nt = 0; nt < 4; nt++) {
            const int c0 = pBase + wn + nt * 8 + 2 * t4;
            float v0 = acc[mt][nt][0] + bi0;
            float v1 = acc[mt][nt][1] + bi0;
            float v2 = acc[mt][nt][2] + bi1;
            float v3 = acc[mt][nt][3] + bi1;
            v0 = (v0 > 0.f) ? v0 : 0.2f * v0;
            v1 = (v1 > 0.f) ? v1 : 0.2f * v1;
            v2 = (v2 > 0.f) ? v2 : 0.2f * v2;
            v3 = (v3 > 0.f) ? v3 : 0.2f * v3;
            *(float2*)&out[(size_t)bt * CHW + (size_t)r0 * HW + c0] = make_float2(v0, v1);
            *(float2*)&out[(size_t)bt * CHW + (size_t)(r0 + 8) * HW + c0] = make_float2(v2, v3);
        }
    }
}

// =====================================================================
// Launch
// =====================================================================
extern "C" void kernel_launch(void* const* d_in, const int* in_sizes, int n_in,
                              void* d_out, int out_size)
{
    (void)in_sizes; (void)n_in; (void)out_size;
    const float* x  = (const float*)d_in[0];
    // d_in[1] = m : dead code in the reference (masked_fill result discarded)
    const float* wq = (const float*)d_in[2];
    const float* bq = (const float*)d_in[3];
    const float* wk = (const float*)d_in[4];
    const float* bk = (const float*)d_in[5];
    const float* wv = (const float*)d_in[6];
    const float* bv = (const float*)d_in[7];
    const float* wo = (const float*)d_in[8];
    const float* bo = (const float*)d_in[9];
    float* out = (float*)d_out;

    // Unconditional (no static guard — harness rule). Idempotent + deterministic.
    cudaFuncSetAttribute(flash3, cudaFuncAttributeMaxDynamicSharedMemorySize,
                         F3_SMEM_BYTES);

    qkv_proj_tc<<<dim3(16, 4, 16), 128>>>(x, wq, bq, wk, bk, wv, bv);

    struct ScaleCfg { int p, o, lp, lo, dd, L, sBase, splitK; };
    const ScaleCfg cfgs[4] = {
        {8,  4, 3, 2, 4096,  128,   0, 32},
        {4,  8, 2, 3, 1024,  512,  64, 16},
        {2, 16, 1, 4,  256, 2048, 128,  1},
        {1, 32, 0, 5,   64, 8192, 192,  1},
    };

    for (int s = 0; s < 4; s++) {
        const ScaleCfg c = cfgs[s];
        const int total = 2 * c.L * c.dd;
        const float qscale = 1.0f / sqrtf((float)c.dd);
        patch_qkv<<<(total + 255) / 256, 256>>>(c.p, c.o, c.dd, c.L, c.sBase, qscale);
        if (s == 3) {
            flash3<<<dim3(128, 2), 128, F3_SMEM_BYTES>>>();
            continue;
        }
        if (c.splitK > 1) {
            const int n = 2 * c.L * c.L;
            zero_scores<<<(n / 4 + 255) / 256, 256>>>(n);
        }
        gemm_scores_tc<<<dim3(c.L / 64, c.L / 64, 2 * c.splitK), 128>>>(c.L, c.dd, c.splitK);
        softmax_rows<<<2 * c.L, 256>>>(c.L);
        gemm_pv_tc<<<dim3(c.dd / 64, c.L / 64, 2), 128>>>(c.L, c.dd, c.lp, c.lo, c.sBase);
    }

    conv3_leaky_tc<<<dim3(16, 4, 16), 128>>>(wo, bo, out);
}

// round 5
// speedup vs baseline: 2.3501x; 1.0376x over previous
#include <cuda_runtime.h>
#include <math.h>

// Problem constants (fixed shapes from the reference)
#define BT   16          // B*T
#define DCH  256         // channels D
#define HW   1024        // 32*32
#define CHW  (DCH*HW)    // 262144

// ---------------- static scratch ----------------
__device__ float g_q[BT * CHW];
__device__ float g_k[BT * CHW];
__device__ float g_v[BT * CHW];
__device__ float g_qs[2 * 524288];   // [b, L, dd] ; scales 0-2 only
__device__ float g_ks[2 * 524288];
__device__ float g_vs[2 * 524288];
__device__ float g_att[BT * CHW];    // concat of per-scale attention outputs
__device__ float g_sc[2ll * 2048 * 2048];  // scores scratch (scales 0-2)

// ---------------- tf32 mma helpers ----------------
__device__ __forceinline__ unsigned f2tf(float f) {
    unsigned u;
    asm("cvt.rna.tf32.f32 %0, %1;" : "=r"(u) : "f"(f));
    return u;
}

__device__ __forceinline__ void mma_tf32(float c[4],
                                         unsigned a0, unsigned a1, unsigned a2, unsigned a3,
                                         unsigned b0, unsigned b1)
{
    asm volatile(
        "mma.sync.aligned.m16n8k8.row.col.f32.tf32.tf32.f32 "
        "{%0,%1,%2,%3}, {%4,%5,%6,%7}, {%8,%9}, {%0,%1,%2,%3};"
        : "+f"(c[0]), "+f"(c[1]), "+f"(c[2]), "+f"(c[3])
        : "r"(a0), "r"(a1), "r"(a2), "r"(a3), "r"(b0), "r"(b1));
}

__device__ __forceinline__ uint4 tf4(float4 v) {
    uint4 u;
    u.x = f2tf(v.x); u.y = f2tf(v.y); u.z = f2tf(v.z); u.w = f2tf(v.w);
    return u;
}

// =====================================================================
// 1) Fused QKV projection (tf32 TC, software-pipelined)
// =====================================================================
__global__ void qkv_proj_tc(const float* __restrict__ x,
                            const float* __restrict__ wq, const float* __restrict__ bq,
                            const float* __restrict__ wk, const float* __restrict__ bk,
                            const float* __restrict__ wv, const float* __restrict__ bv)
{
    const int bt    = blockIdx.z;
    const int oBase = blockIdx.y * 64;
    const int pBase = blockIdx.x * 64;

    __shared__ unsigned Aq[64][20], Ak[64][20], Av[64][20];
    __shared__ unsigned Bs[16][68];

    const int tid  = threadIdx.x;
    const int lane = tid & 31, warp = tid >> 5;
    const int wm = (warp & 1) * 32, wn = (warp >> 1) * 32;
    const int g = lane >> 2, t4 = lane & 3;

    const int rowA = tid >> 1;
    const int offA = (tid & 1) * 8;
    const int rowB = tid >> 3;
    const int offB = (tid & 7) * 8;

    float acc[3][2][4][4];
    #pragma unroll
    for (int s = 0; s < 3; s++)
        #pragma unroll
        for (int mt = 0; mt < 2; mt++)
            #pragma unroll
            for (int nt = 0; nt < 4; nt++)
                #pragma unroll
                for (int e = 0; e < 4; e++) acc[s][mt][nt][e] = 0.f;

    const float* xb = x + (size_t)bt * CHW;

    float4 q0, q1, k0v, k1v, v0, v1, b0, b1;
    #define QKV_LOAD(K0)                                                              \
        q0  = *(const float4*)&wq[(oBase + rowA) * 256 + (K0) + offA];                \
        q1  = *(const float4*)&wq[(oBase + rowA) * 256 + (K0) + offA + 4];            \
        k0v = *(const float4*)&wk[(oBase + rowA) * 256 + (K0) + offA];                \
        k1v = *(const float4*)&wk[(oBase + rowA) * 256 + (K0) + offA + 4];            \
        v0  = *(const float4*)&wv[(oBase + rowA) * 256 + (K0) + offA];                \
        v1  = *(const float4*)&wv[(oBase + rowA) * 256 + (K0) + offA + 4];            \
        b0  = *(const float4*)&xb[(size_t)((K0) + rowB) * HW + pBase + offB];         \
        b1  = *(const float4*)&xb[(size_t)((K0) + rowB) * HW + pBase + offB + 4];

    QKV_LOAD(0)

    for (int k0 = 0; k0 < 256; k0 += 16) {
        __syncthreads();
        *(uint4*)&Aq[rowA][offA]     = tf4(q0);
        *(uint4*)&Aq[rowA][offA + 4] = tf4(q1);
        *(uint4*)&Ak[rowA][offA]     = tf4(k0v);
        *(uint4*)&Ak[rowA][offA + 4] = tf4(k1v);
        *(uint4*)&Av[rowA][offA]     = tf4(v0);
        *(uint4*)&Av[rowA][offA + 4] = tf4(v1);
        *(uint4*)&Bs[rowB][offB]     = tf4(b0);
        *(uint4*)&Bs[rowB][offB + 4] = tf4(b1);
        __syncthreads();
        if (k0 + 16 < 256) { QKV_LOAD(k0 + 16) }
        #pragma unroll
        for (int kk = 0; kk < 16; kk += 8) {
            unsigned bf[4][2];
            #pragma unroll
            for (int nt = 0; nt < 4; nt++) {
                bf[nt][0] = Bs[kk + t4][wn + nt * 8 + g];
                bf[nt][1] = Bs[kk + t4 + 4][wn + nt * 8 + g];
            }
            #pragma unroll
            for (int mt = 0; mt < 2; mt++) {
                const int mr = wm + mt * 16 + g;
                unsigned aq0 = Aq[mr][kk + t4],     aq1 = Aq[mr + 8][kk + t4];
                unsigned aq2 = Aq[mr][kk + t4 + 4], aq3 = Aq[mr + 8][kk + t4 + 4];
                unsigned ak0 = Ak[mr][kk + t4],     ak1 = Ak[mr + 8][kk + t4];
                unsigned ak2 = Ak[mr][kk + t4 + 4], ak3 = Ak[mr + 8][kk + t4 + 4];
                unsigned av0 = Av[mr][kk + t4],     av1 = Av[mr + 8][kk + t4];
                unsigned av2 = Av[mr][kk + t4 + 4], av3 = Av[mr + 8][kk + t4 + 4];
                #pragma unroll
                for (int nt = 0; nt < 4; nt++) {
                    mma_tf32(acc[0][mt][nt], aq0, aq1, aq2, aq3, bf[nt][0], bf[nt][1]);
                    mma_tf32(acc[1][mt][nt], ak0, ak1, ak2, ak3, bf[nt][0], bf[nt][1]);
                    mma_tf32(acc[2][mt][nt], av0, av1, av2, av3, bf[nt][0], bf[nt][1]);
                }
            }
        }
    }

    #pragma unroll
    for (int mt = 0; mt < 2; mt++) {
        const int r0 = oBase + wm + mt * 16 + g;
        const float bq0 = bq[r0], bq1 = bq[r0 + 8];
        const float bk0 = bk[r0], bk1 = bk[r0 + 8];
        const float bv0 = bv[r0], bv1 = bv[r0 + 8];
        #pragma unroll
        for (int nt = 0; nt < 4; nt++) {
            const int c0 = pBase + wn + nt * 8 + 2 * t4;
            const size_t o0 = (size_t)bt * CHW + (size_t)r0 * HW + c0;
            const size_t o1 = (size_t)bt * CHW + (size_t)(r0 + 8) * HW + c0;
            *(float2*)&g_q[o0] = make_float2(acc[0][mt][nt][0] + bq0, acc[0][mt][nt][1] + bq0);
            *(float2*)&g_q[o1] = make_float2(acc[0][mt][nt][2] + bq1, acc[0][mt][nt][3] + bq1);
            *(float2*)&g_k[o0] = make_float2(acc[1][mt][nt][0] + bk0, acc[1][mt][nt][1] + bk0);
            *(float2*)&g_k[o1] = make_float2(acc[1][mt][nt][2] + bk1, acc[1][mt][nt][3] + bk1);
            *(float2*)&g_v[o0] = make_float2(acc[2][mt][nt][0] + bv0, acc[2][mt][nt][1] + bv0);
            *(float2*)&g_v[o1] = make_float2(acc[2][mt][nt][2] + bv1, acc[2][mt][nt][3] + bv1);
        }
    }
}

// =====================================================================
// 2) Patch gather (scales 0-2 only)
// =====================================================================
__global__ void patch_qkv(int p, int o, int dd, int L, int sBase, float qscale)
{
    const int idx = blockIdx.x * 256 + threadIdx.x;
    const int total = 2 * L * dd;
    if (idx >= total) return;
    const int b   = idx / (L * dd);
    const int rem = idx % (L * dd);
    const int l   = rem / dd;
    const int d   = rem % dd;
    const int t   = l / (o * o);
    const int r2  = l % (o * o);
    const int oy  = r2 / o, ox = r2 % o;
    const int c   = d / (p * p);
    const int r3  = d % (p * p);
    const int py  = r3 / p, px = r3 % p;
    const size_t src = ((size_t)(b * 8 + t) * DCH + (sBase + c)) * HW
                     + (oy * p + py) * 32 + (ox * p + px);
    g_qs[idx] = g_q[src] * qscale;
    g_ks[idx] = g_k[src];
    g_vs[idx] = g_v[src];
}

__global__ void zero_scores(int n)
{
    int i = (blockIdx.x * 256 + threadIdx.x) * 4;
    if (i < n) *(float4*)&g_sc[i] = make_float4(0.f, 0.f, 0.f, 0.f);
}

// =====================================================================
// 3) Scores (tf32 TC, NT, pipelined) for scales 0-2
// =====================================================================
__global__ void gemm_scores_tc(int L, int dd, int splitK)
{
    const int bz    = blockIdx.z;
    const int batch = bz / splitK;
    const int ksp   = bz % splitK;
    const int kLen  = dd / splitK;
    const float* __restrict__ A = g_qs + (size_t)batch * L * dd;
    const float* __restrict__ B = g_ks + (size_t)batch * L * dd;
    float* C = g_sc + (size_t)batch * L * L;
    const int mBase = blockIdx.y * 64;
    const int nBase = blockIdx.x * 64;

    __shared__ unsigned As[64][20], Bs[64][20];

    const int tid  = threadIdx.x;
    const int lane = tid & 31, warp = tid >> 5;
    const int wm = (warp & 1) * 32, wn = (warp >> 1) * 32;
    const int g = lane >> 2, t4 = lane & 3;
    const int rowL = tid >> 1;
    const int offL = (tid & 1) * 8;

    float acc[2][4][4];
    #pragma unroll
    for (int mt = 0; mt < 2; mt++)
        #pragma unroll
        for (int nt = 0; nt < 4; nt++)
            #pragma unroll
            for (int e = 0; e < 4; e++) acc[mt][nt][e] = 0.f;

    const int kBeg = ksp * kLen;
    const int kEnd = kBeg + kLen;
    float4 a0, a1, b0, b1;
    #define SC_LOAD(K0)                                                           \
        a0 = *(const float4*)&A[(size_t)(mBase + rowL) * dd + (K0) + offL];       \
        a1 = *(const float4*)&A[(size_t)(mBase + rowL) * dd + (K0) + offL + 4];   \
        b0 = *(const float4*)&B[(size_t)(nBase + rowL) * dd + (K0) + offL];       \
        b1 = *(const float4*)&B[(size_t)(nBase + rowL) * dd + (K0) + offL + 4];

    SC_LOAD(kBeg)

    for (int k0 = kBeg; k0 < kEnd; k0 += 16) {
        __syncthreads();
        *(uint4*)&As[rowL][offL]     = tf4(a0);
        *(uint4*)&As[rowL][offL + 4] = tf4(a1);
        *(uint4*)&Bs[rowL][offL]     = tf4(b0);
        *(uint4*)&Bs[rowL][offL + 4] = tf4(b1);
        __syncthreads();
        if (k0 + 16 < kEnd) { SC_LOAD(k0 + 16) }
        #pragma unroll
        for (int kk = 0; kk < 16; kk += 8) {
            unsigned af[2][4], bf[4][2];
            #pragma unroll
            for (int mt = 0; mt < 2; mt++) {
                const int mr = wm + mt * 16 + g;
                af[mt][0] = As[mr][kk + t4];
                af[mt][1] = As[mr + 8][kk + t4];
                af[mt][2] = As[mr][kk + t4 + 4];
                af[mt][3] = As[mr + 8][kk + t4 + 4];
            }
            #pragma unroll
            for (int nt = 0; nt < 4; nt++) {
                bf[nt][0] = Bs[wn + nt * 8 + g][kk + t4];
                bf[nt][1] = Bs[wn + nt * 8 + g][kk + t4 + 4];
            }
            #pragma unroll
            for (int mt = 0; mt < 2; mt++)
                #pragma unroll
                for (int nt = 0; nt < 4; nt++)
                    mma_tf32(acc[mt][nt], af[mt][0], af[mt][1], af[mt][2], af[mt][3],
                             bf[nt][0], bf[nt][1]);
        }
    }

    #pragma unroll
    for (int mt = 0; mt < 2; mt++) {
        const int r0 = mBase + wm + mt * 16 + g;
        #pragma unroll
        for (int nt = 0; nt < 4; nt++) {
            const int c0 = nBase + wn + nt * 8 + 2 * t4;
            if (splitK == 1) {
                *(float2*)&C[(size_t)r0 * L + c0] =
                    make_float2(acc[mt][nt][0], acc[mt][nt][1]);
                *(float2*)&C[(size_t)(r0 + 8) * L + c0] =
                    make_float2(acc[mt][nt][2], acc[mt][nt][3]);
            } else {
                atomicAdd(&C[(size_t)r0 * L + c0],       acc[mt][nt][0]);
                atomicAdd(&C[(size_t)r0 * L + c0 + 1],   acc[mt][nt][1]);
                atomicAdd(&C[(size_t)(r0 + 8) * L + c0],     acc[mt][nt][2]);
                atomicAdd(&C[(size_t)(r0 + 8) * L + c0 + 1], acc[mt][nt][3]);
            }
        }
    }
}

// =====================================================================
// 4) Row softmax (scales 0-2, L<=2048)
// =====================================================================
__global__ void softmax_rows(int L)
{
    __shared__ float row[2048];
    __shared__ float red[256];
    float* grow = g_sc + (size_t)blockIdx.x * L;
    const int tid = threadIdx.x;
    const int L4 = L >> 2;

    float m = -1e30f;
    for (int i = tid; i < L4; i += 256) {
        float4 v = *(const float4*)&grow[i * 4];
        *(float4*)&row[i * 4] = v;
        m = fmaxf(fmaxf(m, fmaxf(v.x, v.y)), fmaxf(v.z, v.w));
    }
    red[tid] = m; __syncthreads();
    for (int s = 128; s > 0; s >>= 1) {
        if (tid < s) red[tid] = fmaxf(red[tid], red[tid + s]);
        __syncthreads();
    }
    m = red[0];
    __syncthreads();

    float sum = 0.f;
    for (int i = tid; i < L4; i += 256) {
        float4 v = *(const float4*)&row[i * 4];
        v.x = __expf(v.x - m); v.y = __expf(v.y - m);
        v.z = __expf(v.z - m); v.w = __expf(v.w - m);
        *(float4*)&row[i * 4] = v;
        sum += v.x + v.y + v.z + v.w;
    }
    red[tid] = sum; __syncthreads();
    for (int s = 128; s > 0; s >>= 1) {
        if (tid < s) red[tid] += red[tid + s];
        __syncthreads();
    }
    const float inv = 1.0f / red[0];
    __syncthreads();
    for (int i = tid; i < L4; i += 256) {
        float4 v = *(const float4*)&row[i * 4];
        v.x *= inv; v.y *= inv; v.z *= inv; v.w *= inv;
        *(float4*)&grow[i * 4] = v;
    }
}

// =====================================================================
// 5) P·V (tf32 TC, NN, pipelined) with fused un-patch scatter (scales 0-2)
// =====================================================================
__global__ void gemm_pv_tc(int L, int dd, int lp, int lo, int sBase)
{
    const int batch = blockIdx.z;
    const float* __restrict__ A = g_sc + (size_t)batch * L * L;
    const float* __restrict__ B = g_vs + (size_t)batch * L * dd;
    const int mBase = blockIdx.y * 64;
    const int nBase = blockIdx.x * 64;

    __shared__ unsigned As[64][20];
    __shared__ unsigned Bs[16][68];

    const int tid  = threadIdx.x;
    const int lane = tid & 31, warp = tid >> 5;
    const int wm = (warp & 1) * 32, wn = (warp >> 1) * 32;
    const int g = lane >> 2, t4 = lane & 3;
    const int rowA = tid >> 1, offA = (tid & 1) * 8;
    const int rowB = tid >> 3, offB = (tid & 7) * 8;

    float acc[2][4][4];
    #pragma unroll
    for (int mt = 0; mt < 2; mt++)
        #pragma unroll
        for (int nt = 0; nt < 4; nt++)
            #pragma unroll
            for (int e = 0; e < 4; e++) acc[mt][nt][e] = 0.f;

    float4 a0, a1, b0, b1;
    #define PV_LOAD(K0)                                                            \
        a0 = *(const float4*)&A[(size_t)(mBase + rowA) * L + (K0) + offA];         \
        a1 = *(const float4*)&A[(size_t)(mBase + rowA) * L + (K0) + offA + 4];     \
        b0 = *(const float4*)&B[(size_t)((K0) + rowB) * dd + nBase + offB];        \
        b1 = *(const float4*)&B[(size_t)((K0) + rowB) * dd + nBase + offB + 4];

    PV_LOAD(0)

    for (int k0 = 0; k0 < L; k0 += 16) {
        __syncthreads();
        *(uint4*)&As[rowA][offA]     = tf4(a0);
        *(uint4*)&As[rowA][offA + 4] = tf4(a1);
        *(uint4*)&Bs[rowB][offB]     = tf4(b0);
        *(uint4*)&Bs[rowB][offB + 4] = tf4(b1);
        __syncthreads();
        if (k0 + 16 < L) { PV_LOAD(k0 + 16) }
        #pragma unroll
        for (int kk = 0; kk < 16; kk += 8) {
            unsigned af[2][4], bf[4][2];
            #pragma unroll
            for (int mt = 0; mt < 2; mt++) {
                const int mr = wm + mt * 16 + g;
                af[mt][0] = As[mr][kk + t4];
                af[mt][1] = As[mr + 8][kk + t4];
                af[mt][2] = As[mr][kk + t4 + 4];
                af[mt][3] = As[mr + 8][kk + t4 + 4];
            }
            #pragma unroll
            for (int nt = 0; nt < 4; nt++) {
                bf[nt][0] = Bs[kk + t4][wn + nt * 8 + g];
                bf[nt][1] = Bs[kk + t4 + 4][wn + nt * 8 + g];
            }
            #pragma unroll
            for (int mt = 0; mt < 2; mt++)
                #pragma unroll
                for (int nt = 0; nt < 4; nt++)
                    mma_tf32(acc[mt][nt], af[mt][0], af[mt][1], af[mt][2], af[mt][3],
                             bf[nt][0], bf[nt][1]);
        }
    }

    const int oo = 1 << lo, pp = 1 << lp;
    #pragma unroll
    for (int mt = 0; mt < 2; mt++) {
        #pragma unroll
        for (int nt = 0; nt < 4; nt++) {
            #pragma unroll
            for (int e = 0; e < 4; e++) {
                const int l = mBase + wm + mt * 16 + g + (e >= 2 ? 8 : 0);
                const int d = nBase + wn + nt * 8 + 2 * t4 + (e & 1);
                const int t  = l >> (2 * lo);
                const int r2 = l & (oo * oo - 1);
                const int oy = r2 >> lo, ox = r2 & (oo - 1);
                const int c  = d >> (2 * lp);
                const int r3 = d & (pp * pp - 1);
                const int py = r3 >> lp, px = r3 & (pp - 1);
                const size_t dst = ((size_t)(batch * 8 + t) * DCH + sBase + c) * HW
                                 + (size_t)(((oy << lp) + py) * 32 + (ox << lp) + px);
                g_att[dst] = acc[mt][nt][e];
            }
        }
    }
}

// =====================================================================
// 5b) Flash attention scale 3 (L=8192, dd=64, p=1, sBase=192), fused gather.
//     grid (64, 2), 256 threads (8 warps). BM=128 q rows, BN=64 k rows/iter.
//     Channel-major smem tiles (natural gmem layout, no transpose cost):
//       Qs[64][132] (d, r), Ks[64][68] (d, r), Vs[64][68] (d, r), Ps[8][16][68]
//     Software-pipelined K/V tile prefetch into registers.
// =====================================================================
#define F3_QST 132
#define F3_KST 68
#define F3_SMEM_WORDS (64 * F3_QST + 2 * 64 * F3_KST + 8 * 16 * F3_KST)
#define F3_SMEM_BYTES (F3_SMEM_WORDS * 4)   // 103424
__global__ void flash3()
{
    extern __shared__ unsigned sm[];
    unsigned* Qs = sm;                          // [64][132] (d-major)
    unsigned* Ks = Qs + 64 * F3_QST;            // [64][68]  (d-major)
    unsigned* Vs = Ks + 64 * F3_KST;            // [64][68]  (d-major)
    unsigned* Ps = Vs + 64 * F3_KST;            // [8][16][68]

    const int batch = blockIdx.y;
    const int qBase = blockIdx.x * 128;         // 64 q-tiles per batch
    const int tid  = threadIdx.x;               // 256
    const int lane = tid & 31, warp = tid >> 5; // 8 warps
    const int g = lane >> 2, t4 = lane & 3;
    const int wr = warp * 16;
    unsigned* Pw = Ps + warp * 16 * F3_KST;

    // Scale-3 view: l = t*1024 + pix, d = channel-192. qBase tile within one t.
    const int bt_q = batch * 8 + (qBase >> 10);
    const int pix0 = qBase & 1023;
    const float* Qg = g_q + ((size_t)bt_q * DCH + 192) * HW + pix0;
    const float qscale = 0.125f;   // 1/sqrt(64)

    // Load Q tile: 64 channels x 128 pixels (coalesced, contiguous smem rows)
    #pragma unroll
    for (int j = 0; j < 8; j++) {
        const int idx = j * 256 + tid;
        const int d = idx >> 5, r4 = (idx & 31) * 4;
        float4 v = *(const float4*)&Qg[(size_t)d * HW + r4];
        v.x *= qscale; v.y *= qscale; v.z *= qscale; v.w *= qscale;
        *(uint4*)&Qs[d * F3_QST + r4] = tf4(v);
    }

    float oacc[8][4];
    #pragma unroll
    for (int nt = 0; nt < 8; nt++)
        #pragma unroll
        for (int e = 0; e < 4; e++) oacc[nt][e] = 0.f;
    float m0 = -1e30f, m1 = -1e30f, l0 = 0.f, l1 = 0.f;

    // prefetch K/V tile 0
    const int d_ld = tid >> 4;                  // rows loaded by this thread (per j offset +16)
    const int r4_ld = (tid & 15) * 4;
    float4 kreg[4], vreg[4];
    {
        const int bt_k = batch * 8;             // kBase=0 -> t=0
        const float* Kg = g_k + ((size_t)bt_k * DCH + 192) * HW;
        const float* Vg = g_v + ((size_t)bt_k * DCH + 192) * HW;
        #pragma unroll
        for (int j = 0; j < 4; j++) {
            kreg[j] = *(const float4*)&Kg[(size_t)(d_ld + j * 16) * HW + r4_ld];
            vreg[j] = *(const float4*)&Vg[(size_t)(d_ld + j * 16) * HW + r4_ld];
        }
    }

    for (int kt = 0; kt < 128; kt++) {
        __syncthreads();
        #pragma unroll
        for (int j = 0; j < 4; j++) {
            *(uint4*)&Ks[(d_ld + j * 16) * F3_KST + r4_ld] = tf4(kreg[j]);
            *(uint4*)&Vs[(d_ld + j * 16) * F3_KST + r4_ld] = tf4(vreg[j]);
        }
        __syncthreads();
        if (kt + 1 < 128) {
            const int kBase = (kt + 1) * 64;
            const int bt_k = batch * 8 + (kBase >> 10);
            const int pixk = kBase & 1023;
            const float* Kg = g_k + ((size_t)bt_k * DCH + 192) * HW + pixk;
            const float* Vg = g_v + ((size_t)bt_k * DCH + 192) * HW + pixk;
            #pragma unroll
            for (int j = 0; j < 4; j++) {
                kreg[j] = *(const float4*)&Kg[(size_t)(d_ld + j * 16) * HW + r4_ld];
                vreg[j] = *(const float4*)&Vg[(size_t)(d_ld + j * 16) * HW + r4_ld];
            }
        }

        // S = Q K^T : A[m][kd] = Qs[kd][m], B[n][kd] = Ks[kd][n]
        float sacc[8][4];
        #pragma unroll
        for (int nt = 0; nt < 8; nt++)
            #pragma unroll
            for (int e = 0; e < 4; e++) sacc[nt][e] = 0.f;
        #pragma unroll
        for (int kk = 0; kk < 64; kk += 8) {
            const unsigned a0 = Qs[(kk + t4) * F3_QST + wr + g];
            const unsigned a1 = Qs[(kk + t4) * F3_QST + wr + g + 8];
            const unsigned a2 = Qs[(kk + t4 + 4) * F3_QST + wr + g];
            const unsigned a3 = Qs[(kk + t4 + 4) * F3_QST + wr + g + 8];
            #pragma unroll
            for (int nt = 0; nt < 8; nt++) {
                const unsigned b0 = Ks[(kk + t4) * F3_KST + nt * 8 + g];
                const unsigned b1 = Ks[(kk + t4 + 4) * F3_KST + nt * 8 + g];
                mma_tf32(sacc[nt], a0, a1, a2, a3, b0, b1);
            }
        }

        // online softmax
        float rm0 = -1e30f, rm1 = -1e30f;
        #pragma unroll
        for (int nt = 0; nt < 8; nt++) {
            rm0 = fmaxf(rm0, fmaxf(sacc[nt][0], sacc[nt][1]));
            rm1 = fmaxf(rm1, fmaxf(sacc[nt][2], sacc[nt][3]));
        }
        rm0 = fmaxf(rm0, __shfl_xor_sync(0xffffffff, rm0, 1));
        rm0 = fmaxf(rm0, __shfl_xor_sync(0xffffffff, rm0, 2));
        rm1 = fmaxf(rm1, __shfl_xor_sync(0xffffffff, rm1, 1));
        rm1 = fmaxf(rm1, __shfl_xor_sync(0xffffffff, rm1, 2));

        const float mn0 = fmaxf(m0, rm0);
        const float mn1 = fmaxf(m1, rm1);
        const float al0 = __expf(m0 - mn0);
        const float al1 = __expf(m1 - mn1);
        m0 = mn0; m1 = mn1;

        float ps0 = 0.f, ps1 = 0.f;
        #pragma unroll
        for (int nt = 0; nt < 8; nt++) {
            const float p0 = __expf(sacc[nt][0] - mn0);
            const float p1 = __expf(sacc[nt][1] - mn0);
            const float p2 = __expf(sacc[nt][2] - mn1);
            const float p3 = __expf(sacc[nt][3] - mn1);
            ps0 += p0 + p1; ps1 += p2 + p3;
            const int c = nt * 8 + 2 * t4;
            Pw[g * F3_KST + c]           = f2tf(p0);
            Pw[g * F3_KST + c + 1]       = f2tf(p1);
            Pw[(g + 8) * F3_KST + c]     = f2tf(p2);
            Pw[(g + 8) * F3_KST + c + 1] = f2tf(p3);
        }
        ps0 += __shfl_xor_sync(0xffffffff, ps0, 1);
        ps0 += __shfl_xor_sync(0xffffffff, ps0, 2);
        ps1 += __shfl_xor_sync(0xffffffff, ps1, 1);
        ps1 += __shfl_xor_sync(0xffffffff, ps1, 2);
        l0 = l0 * al0 + ps0;
        l1 = l1 * al1 + ps1;

        #pragma unroll
        for (int nt = 0; nt < 8; nt++) {
            oacc[nt][0] *= al0; oacc[nt][1] *= al0;
            oacc[nt][2] *= al1; oacc[nt][3] *= al1;
        }
        __syncwarp();

        // O += P V : A[m][kl] = Pw[m][kl], B[kl][nd] = Vs[nd][kl]
        #pragma unroll
        for (int kk = 0; kk < 64; kk += 8) {
            const unsigned a0 = Pw[g * F3_KST + kk + t4];
            const unsigned a1 = Pw[(g + 8) * F3_KST + kk + t4];
            const unsigned a2 = Pw[g * F3_KST + kk + t4 + 4];
            const unsigned a3 = Pw[(g + 8) * F3_KST + kk + t4 + 4];
            #pragma unroll
            for (int nt = 0; nt < 8; nt++) {
                const unsigned b0 = Vs[(nt * 8 + g) * F3_KST + kk + t4];
                const unsigned b1 = Vs[(nt * 8 + g) * F3_KST + kk + t4 + 4];
                mma_tf32(oacc[nt], a0, a1, a2, a3, b0, b1);
            }
        }
        __syncwarp();
    }

    // epilogue: normalize + scatter (p=1: channel 192+d, pixel pix0+row)
    const float inv0 = 1.0f / l0;
    const float inv1 = 1.0f / l1;
    const int px0 = pix0 + wr + g;
    const int px1 = px0 + 8;
    float* Og = g_att + (size_t)bt_q * CHW + (size_t)192 * HW;
    #pragma unroll
    for (int nt = 0; nt < 8; nt++) {
        const int d = nt * 8 + 2 * t4;
        Og[(size_t)d * HW + px0]       = oacc[nt][0] * inv0;
        Og[(size_t)(d + 1) * HW + px0] = oacc[nt][1] * inv0;
        Og[(size_t)d * HW + px1]       = oacc[nt][2] * inv1;
        Og[(size_t)(d + 1) * HW + px1] = oacc[nt][3] * inv1;
    }
}

// =====================================================================
// 6) 3x3 SAME conv (tf32 TC implicit GEMM, pipelined) + bias + LeakyReLU
// =====================================================================
__global__ void conv3_leaky_tc(const float* __restrict__ wo, const float* __restrict__ bo,
                               float* __restrict__ out)
{
    const int bt    = blockIdx.z;
    const int oBase = blockIdx.y * 64;
    const int pBase = blockIdx.x * 64;

    __shared__ unsigned As[64][20];
    __shared__ unsigned Bs[16][68];

    const int tid  = threadIdx.x;
    const int lane = tid & 31, warp = tid >> 5;
    const int wm = (warp & 1) * 32, wn = (warp >> 1) * 32;
    const int g = lane >> 2, t4 = lane & 3;
    const int rowA = tid >> 1, offA = (tid & 1) * 8;
    const int rowB = tid >> 3, offB = (tid & 7) * 8;

    float acc[2][4][4];
    #pragma unroll
    for (int mt = 0; mt < 2; mt++)
        #pragma unroll
        for (int nt = 0; nt < 4; nt++)
            #pragma unroll
            for (int e = 0; e < 4; e++) acc[mt][nt][e] = 0.f;

    const float* inb = g_att + (size_t)bt * CHW;

    float4 a0, a1;
    float bv[8];
    #define CONV_LOAD(K0)                                                             \
        a0 = *(const float4*)&wo[(size_t)(oBase + rowA) * 2304 + (K0) + offA];        \
        a1 = *(const float4*)&wo[(size_t)(oBase + rowA) * 2304 + (K0) + offA + 4];    \
        {                                                                             \
            const int k  = (K0) + rowB;                                               \
            const int ic = k / 9;                                                     \
            const int r  = k % 9;                                                     \
            const int ky = r / 3 - 1, kx = r % 3 - 1;                                 \
            _Pragma("unroll")                                                         \
            for (int q = 0; q < 8; q++) {                                             \
                const int ppix = pBase + offB + q;                                    \
                const int y  = (ppix >> 5) + ky;                                      \
                const int xx = (ppix & 31) + kx;                                      \
                bv[q] = (y >= 0 && y < 32 && xx >= 0 && xx < 32)                      \
                      ? inb[(size_t)ic * HW + y * 32 + xx] : 0.f;                     \
            }                                                                         \
        }

    CONV_LOAD(0)

    for (int k0 = 0; k0 < 2304; k0 += 16) {
        __syncthreads();
        *(uint4*)&As[rowA][offA]     = tf4(a0);
        *(uint4*)&As[rowA][offA + 4] = tf4(a1);
        #pragma unroll
        for (int q = 0; q < 8; q++) Bs[rowB][offB + q] = f2tf(bv[q]);
        __syncthreads();
        if (k0 + 16 < 2304) { CONV_LOAD(k0 + 16) }
        #pragma unroll
        for (int kk = 0; kk < 16; kk += 8) {
            unsigned af[2][4], bf[4][2];
            #pragma unroll
            for (int mt = 0; mt < 2; mt++) {
                const int mr = wm + mt * 16 + g;
                af[mt][0] = As[mr][kk + t4];
                af[mt][1] = As[mr + 8][kk + t4];
                af[mt][2] = As[mr][kk + t4 + 4];
                af[mt][3] = As[mr + 8][kk + t4 + 4];
            }
            #pragma unroll
            for (int nt = 0; nt < 4; nt++) {
                bf[nt][0] = Bs[kk + t4][wn + nt * 8 + g];
                bf[nt][1] = Bs[kk + t4 + 4][wn + nt * 8 + g];
            }
            #pragma unroll
            for (int mt = 0; mt < 2; mt++)
                #pragma unroll
                for (int nt = 0; nt < 4; nt++)
                    mma_tf32(acc[mt][nt], af[mt][0], af[mt][1], af[mt][2], af[mt][3],
                             bf[nt][0], bf[nt][1]);
        }
    }

    #pragma unroll
    for (int mt = 0; mt < 2; mt++) {
        const int r0 = oBase + wm + mt * 16 + g;
        const float bi0 = bo[r0], bi1 = bo[r0 + 8];
        #pragma unroll
        for (int nt = 0; nt < 4; nt++) {
            const int c0 = pBase + wn + nt * 8 + 2 * t4;
            float v0 = acc[mt][nt][0] + bi0;
            float v1 = acc[mt][nt][1] + bi0;
            float v2 = acc[mt][nt][2] + bi1;
            float v3 = acc[mt][nt][3] + bi1;
            v0 = (v0 > 0.f) ? v0 : 0.2f * v0;
            v1 = (v1 > 0.f) ? v1 : 0.2f * v1;
            v2 = (v2 > 0.f) ? v2 : 0.2f * v2;
            v3 = (v3 > 0.f) ? v3 : 0.2f * v3;
            *(float2*)&out[(size_t)bt * CHW + (size_t)r0 * HW + c0] = make_float2(v0, v1);
            *(float2*)&out[(size_t)bt * CHW + (size_t)(r0 + 8) * HW + c0] = make_float2(v2, v3);
        }
    }
}

// =====================================================================
// Launch
// =====================================================================
extern "C" void kernel_launch(void* const* d_in, const int* in_sizes, int n_in,
                              void* d_out, int out_size)
{
    (void)in_sizes; (void)n_in; (void)out_size;
    const float* x  = (const float*)d_in[0];
    // d_in[1] = m : dead code in the reference (masked_fill result discarded)
    const float* wq = (const float*)d_in[2];
    const float* bq = (const float*)d_in[3];
    const float* wk = (const float*)d_in[4];
    const float* bk = (const float*)d_in[5];
    const float* wv = (const float*)d_in[6];
    const float* bv = (const float*)d_in[7];
    const float* wo = (const float*)d_in[8];
    const float* bo = (const float*)d_in[9];
    float* out = (float*)d_out;

    // Unconditional (no static guard). Idempotent + deterministic.
    cudaFuncSetAttribute(flash3, cudaFuncAttributeMaxDynamicSharedMemorySize,
                         F3_SMEM_BYTES);

    qkv_proj_tc<<<dim3(16, 4, 16), 128>>>(x, wq, bq, wk, bk, wv, bv);

    struct ScaleCfg { int p, o, lp, lo, dd, L, sBase, splitK; };
    const ScaleCfg cfgs[4] = {
        {8,  4, 3, 2, 4096,  128,   0, 32},
        {4,  8, 2, 3, 1024,  512,  64, 16},
        {2, 16, 1, 4,  256, 2048, 128,  1},
        {1, 32, 0, 5,   64, 8192, 192,  1},
    };

    for (int s = 0; s < 4; s++) {
        const ScaleCfg c = cfgs[s];
        if (s == 3) {
            flash3<<<dim3(64, 2), 256, F3_SMEM_BYTES>>>();
            continue;
        }
        const int total = 2 * c.L * c.dd;
        const float qscale = 1.0f / sqrtf((float)c.dd);
        patch_qkv<<<(total + 255) / 256, 256>>>(c.p, c.o, c.dd, c.L, c.sBase, qscale);
        if (c.splitK > 1) {
            const int n = 2 * c.L * c.L;
            zero_scores<<<(n / 4 + 255) / 256, 256>>>(n);
        }
        gemm_scores_tc<<<dim3(c.L / 64, c.L / 64, 2 * c.splitK), 128>>>(c.L, c.dd, c.splitK);
        softmax_rows<<<2 * c.L, 256>>>(c.L);
        gemm_pv_tc<<<dim3(c.dd / 64, c.L / 64, 2), 128>>>(c.L, c.dd, c.lp, c.lo, c.sBase);
    }

    conv3_leaky_tc<<<dim3(16, 4, 16), 128>>>(wo, bo, out);
}